// round 11
// baseline (speedup 1.0000x reference)
#include <cuda_runtime.h>
#include <cuda_fp16.h>
#include <math.h>
#include <stdint.h>

// Problem constants
#define BATCH 2
#define SEQ   1024
#define HID   5120
#define NHEAD 40
#define HDIM  128
#define QKV_N (3*HID)          // 15360
#define MROWS (BATCH*SEQ)      // 2048

// ---------------------------------------------------------------------------
// Scratch (fp16)
// ---------------------------------------------------------------------------
__device__ __half g_qkvh[(size_t)MROWS * QKV_N];
__device__ __half g_qkvl[(size_t)MROWS * HID];     // lo only needed for Q region
__device__ __half g_hh[(size_t)MROWS * HID];
__device__ __half g_hl[(size_t)MROWS * HID];
__device__ __half g_ah[(size_t)MROWS * HID];
__device__ __half g_al[(size_t)MROWS * HID];
__device__ __half g_wph[(size_t)QKV_N * HID];
__device__ __half g_woh[(size_t)HID * HID];

// ---------------------------------------------------------------------------
// PTX helpers (compute_103-safe)
// ---------------------------------------------------------------------------
__device__ __forceinline__ uint32_t smem_u32(const void* p) {
    uint32_t a;
    asm("{ .reg .u64 t; cvta.to.shared.u64 t, %1; cvt.u32.u64 %0, t; }"
        : "=r"(a) : "l"(p));
    return a;
}

#define CP_ASYNC16(dst, src) \
    asm volatile("cp.async.cg.shared.global [%0], [%1], 16;" \
        :: "r"(dst), "l"(src))
#define CP_COMMIT() asm volatile("cp.async.commit_group;" ::: "memory")
#define CP_WAIT(n)  asm volatile("cp.async.wait_group %0;" :: "n"(n) : "memory")

__device__ __forceinline__ void ldm_x4(uint32_t* r, uint32_t addr) {
    asm volatile("ldmatrix.sync.aligned.m8n8.x4.shared.b16 {%0,%1,%2,%3}, [%4];"
        : "=r"(r[0]), "=r"(r[1]), "=r"(r[2]), "=r"(r[3]) : "r"(addr));
}
__device__ __forceinline__ void ldm_x4_t(uint32_t* r, uint32_t addr) {
    asm volatile("ldmatrix.sync.aligned.m8n8.x4.trans.shared.b16 {%0,%1,%2,%3}, [%4];"
        : "=r"(r[0]), "=r"(r[1]), "=r"(r[2]), "=r"(r[3]) : "r"(addr));
}

// fp32-accumulator HMMA
__device__ __forceinline__ void mma_f16(float* d, const uint32_t* a,
                                        uint32_t b0, uint32_t b1) {
    asm volatile(
        "mma.sync.aligned.m16n8k16.row.col.f32.f16.f16.f32 "
        "{%0,%1,%2,%3}, {%4,%5,%6,%7}, {%8,%9}, {%0,%1,%2,%3};"
        : "+f"(d[0]), "+f"(d[1]), "+f"(d[2]), "+f"(d[3])
        : "r"(a[0]), "r"(a[1]), "r"(a[2]), "r"(a[3]), "r"(b0), "r"(b1));
}

// fp16-accumulator HMMA (for the lo correction term; 2x rate if consumer-split)
__device__ __forceinline__ void mma_f16acc(uint32_t* d, const uint32_t* a,
                                           uint32_t b0, uint32_t b1) {
    asm volatile(
        "mma.sync.aligned.m16n8k16.row.col.f16.f16.f16.f16 "
        "{%0,%1}, {%2,%3,%4,%5}, {%6,%7}, {%0,%1};"
        : "+r"(d[0]), "+r"(d[1])
        : "r"(a[0]), "r"(a[1]), "r"(a[2]), "r"(a[3]), "r"(b0), "r"(b1));
}

// ---------------------------------------------------------------------------
// fp32 -> fp16 hi+lo split / hi-only convert
// ---------------------------------------------------------------------------
__global__ void split_f16(const float* __restrict__ x,
                          __half* __restrict__ hi,
                          __half* __restrict__ lo, size_t n4)
{
    size_t i = (size_t)blockIdx.x * blockDim.x + threadIdx.x;
    if (i >= n4) return;
    float4 v = ((const float4*)x)[i];
    __half h0 = __float2half_rn(v.x);
    __half h1 = __float2half_rn(v.y);
    __half h2 = __float2half_rn(v.z);
    __half h3 = __float2half_rn(v.w);
    __half2 H0; H0.x = h0; H0.y = h1;
    __half2 H1; H1.x = h2; H1.y = h3;
    ((__half2*)hi)[2*i]   = H0;
    ((__half2*)hi)[2*i+1] = H1;
    __half2 L0, L1;
    L0.x = __float2half_rn(v.x - __half2float(h0));
    L0.y = __float2half_rn(v.y - __half2float(h1));
    L1.x = __float2half_rn(v.z - __half2float(h2));
    L1.y = __float2half_rn(v.w - __half2float(h3));
    ((__half2*)lo)[2*i]   = L0;
    ((__half2*)lo)[2*i+1] = L1;
}

__global__ void cvt_f16(const float* __restrict__ x,
                        __half* __restrict__ hi, size_t n4)
{
    size_t i = (size_t)blockIdx.x * blockDim.x + threadIdx.x;
    if (i >= n4) return;
    float4 v = ((const float4*)x)[i];
    __half2 H0; H0.x = __float2half_rn(v.x); H0.y = __float2half_rn(v.y);
    __half2 H1; H1.x = __float2half_rn(v.z); H1.y = __float2half_rn(v.w);
    ((__half2*)hi)[2*i]   = H0;
    ((__half2*)hi)[2*i+1] = H1;
}

// ---------------------------------------------------------------------------
// fp16 2-term HMMA GEMM:  C = A @ B^T ≈ Ah·Bh (fp32 acc) + Al·Bh (fp16 acc)
// CTA 128x128, 8 warps (4M x 2N), warp tile 32x64, BK=32, 2-stage cp.async.
// Cf != nullptr -> fp32 out; else fp16 hi/lo out (Cl only for col < lo_limit).
// ---------------------------------------------------------------------------
#define BM 128
#define BN 128
#define BK 32
#define ROWB 80
#define TILEB (128 * ROWB)        // 10240
#define STAGEB (3 * TILEB)        // 30720 (Ah, Al, Bh)
#define GEMM_SMEM (2 * STAGEB)    // 61440
#define GTHREADS 256

__global__ __launch_bounds__(GTHREADS)
void gemm_hmma(const __half* __restrict__ Ah, const __half* __restrict__ Al,
               const __half* __restrict__ Bh,
               float* __restrict__ Cf,
               __half* __restrict__ Ch, __half* __restrict__ Cl, int lo_limit,
               int M, int N, int K)
{
    extern __shared__ char smem[];
    const uint32_t sbase = smem_u32(smem);
    const int tid  = threadIdx.x;
    const int wid  = tid >> 5;
    const int lane = tid & 31;
    const int wm = wid & 3;
    const int wn = wid >> 2;
    const int m0 = blockIdx.x * BM;
    const int n0 = blockIdx.y * BN;
    const int NCH = K / BK;

    // stage loader: 1536 16B chunks, 6 per thread
    auto load_stage = [&](int s, int kc) {
        const int k0 = kc * BK;
#pragma unroll
        for (int j = 0; j < 6; j++) {
            int id   = tid + j * GTHREADS;   // 0..1535
            int tile = id >> 9;              // 0=Ah 1=Al 2=Bh
            int idx  = id & 511;
            int row  = idx >> 2;
            int c16  = idx & 3;
            const __half* sb = (tile == 0) ? Ah : (tile == 1) ? Al : Bh;
            int grow = ((tile < 2) ? m0 : n0) + row;
            const void* src = sb + (size_t)grow * K + k0 + c16 * 8;
            uint32_t dst = sbase + s * STAGEB + tile * TILEB + row * ROWB + c16 * 16;
            CP_ASYNC16(dst, src);
        }
        CP_COMMIT();
    };

    float acc[2][8][4];
    uint32_t accL[2][8][2];
#pragma unroll
    for (int mi = 0; mi < 2; mi++)
#pragma unroll
        for (int nj = 0; nj < 8; nj++) {
#pragma unroll
            for (int q = 0; q < 4; q++) acc[mi][nj][q] = 0.f;
            accL[mi][nj][0] = 0u; accL[mi][nj][1] = 0u;
        }

    load_stage(0, 0);
    if (NCH > 1) load_stage(1, 1);

    const int lr = lane & 15;
    const int lc = (lane >> 4) * 16;
    const uint32_t rowA = (wm * 32 + lr) * ROWB + lc;
    const uint32_t rowB = (wn * 64 + lr) * ROWB + lc;

    for (int c = 0; c < NCH; c++) {
        CP_WAIT(1);
        __syncthreads();

        const uint32_t st  = sbase + (c & 1) * STAGEB;
        const uint32_t sAh = st;
        const uint32_t sAl = st + TILEB;
        const uint32_t sBh = st + 2 * TILEB;

#pragma unroll
        for (int kk = 0; kk < 2; kk++) {
            const uint32_t koff = kk * 32;
            uint32_t ahf[2][4], alf[2][4], bhf[4][4];
#pragma unroll
            for (int mi = 0; mi < 2; mi++) {
                uint32_t ra = rowA + mi * 16 * ROWB + koff;
                ldm_x4(ahf[mi], sAh + ra);
                ldm_x4(alf[mi], sAl + ra);
            }
#pragma unroll
            for (int nj = 0; nj < 4; nj++) {
                uint32_t rb = rowB + nj * 16 * ROWB + koff;
                ldm_x4(bhf[nj], sBh + rb);
            }
            // term 1: Ah * Bh  (fp32 accumulators)
#pragma unroll
            for (int mi = 0; mi < 2; mi++)
#pragma unroll
                for (int nj = 0; nj < 4; nj++) {
                    mma_f16(acc[mi][2*nj],   ahf[mi], bhf[nj][0], bhf[nj][2]);
                    mma_f16(acc[mi][2*nj+1], ahf[mi], bhf[nj][1], bhf[nj][3]);
                }
            // term 2: Al * Bh  (fp16 accumulators — correction term)
#pragma unroll
            for (int mi = 0; mi < 2; mi++)
#pragma unroll
                for (int nj = 0; nj < 4; nj++) {
                    mma_f16acc(accL[mi][2*nj],   alf[mi], bhf[nj][0], bhf[nj][2]);
                    mma_f16acc(accL[mi][2*nj+1], alf[mi], bhf[nj][1], bhf[nj][3]);
                }
        }

        __syncthreads();
        if (c + 2 < NCH) load_stage(c & 1, c + 2);
    }

    // merge fp16 lo accumulators into fp32
#pragma unroll
    for (int mi = 0; mi < 2; mi++)
#pragma unroll
        for (int nj = 0; nj < 8; nj++) {
            float2 lo01 = __half22float2(*(__half2*)&accL[mi][nj][0]);
            float2 lo23 = __half22float2(*(__half2*)&accL[mi][nj][1]);
            acc[mi][nj][0] += lo01.x;
            acc[mi][nj][1] += lo01.y;
            acc[mi][nj][2] += lo23.x;
            acc[mi][nj][3] += lo23.y;
        }

    const int g  = lane >> 2;
    const int cc = (lane & 3) * 2;
#pragma unroll
    for (int mi = 0; mi < 2; mi++) {
        const int rbase = m0 + wm * 32 + mi * 16;
#pragma unroll
        for (int nj = 0; nj < 8; nj++) {
            const int cbase = n0 + wn * 64 + nj * 8 + cc;
            if (Cf) {
                float2 v0 = make_float2(acc[mi][nj][0], acc[mi][nj][1]);
                float2 v1 = make_float2(acc[mi][nj][2], acc[mi][nj][3]);
                *(float2*)&Cf[(size_t)(rbase + g) * N + cbase]     = v0;
                *(float2*)&Cf[(size_t)(rbase + g + 8) * N + cbase] = v1;
            } else {
#pragma unroll
                for (int rr = 0; rr < 2; rr++) {
                    float x0 = acc[mi][nj][2*rr], x1 = acc[mi][nj][2*rr+1];
                    __half h0 = __float2half_rn(x0);
                    __half h1 = __float2half_rn(x1);
                    __half2 H; H.x = h0; H.y = h1;
                    size_t row = (size_t)(rbase + g + 8*rr);
                    *(__half2*)&Ch[row * N + cbase] = H;
                    if (cbase < lo_limit) {
                        __half2 L;
                        L.x = __float2half_rn(x0 - __half2float(h0));
                        L.y = __float2half_rn(x1 - __half2float(h1));
                        *(__half2*)&Cl[row * lo_limit + cbase] = L;
                    }
                }
            }
        }
    }
}

// ---------------------------------------------------------------------------
// fp16 2-term HMMA flash attention (round 10, unchanged)
// ---------------------------------------------------------------------------
#define AROW 272
#define ATILE (64 * AROW)
#define PROW 144
#define PTILE (64 * PROW)
#define KSTAGE (2 * ATILE)
#define ATTN_SMEM (2*ATILE + 2*KSTAGE + 2*PTILE)   // 122880

__global__ __launch_bounds__(128, 1)
void attn_hmma(const __half* __restrict__ QKVh,
               const __half* __restrict__ Ql_,
               __half* __restrict__ Oh,
               __half* __restrict__ Ol)
{
    extern __shared__ char smem[];
    const uint32_t sb = smem_u32(smem);
    const int tid = threadIdx.x, wid = tid >> 5, lane = tid & 31;
    const int qt = blockIdx.x, h = blockIdx.y, b = blockIdx.z;
    const int q0 = qt * 64;
    const int lr = lane & 15, lc = (lane >> 4) * 16;
    const int g = lane >> 2, t = lane & 3;

    const uint32_t QH_ = sb, QL_ = sb + ATILE;
    const uint32_t KST = sb + 2 * ATILE;
    const uint32_t PH_ = sb + 2 * ATILE + 2 * KSTAGE;
    const uint32_t PL_ = PH_ + PTILE;

#pragma unroll
    for (int j = 0; j < 8; j++) {
        int id = tid + j * 128;
        int row = id >> 4, c16 = id & 15;
        size_t ghoff = (size_t)(b * SEQ + q0 + row) * QKV_N + h * HDIM + c16 * 8;
        size_t gloff = (size_t)(b * SEQ + q0 + row) * HID   + h * HDIM + c16 * 8;
        CP_ASYNC16(QH_ + row * AROW + c16 * 16, QKVh + ghoff);
        CP_ASYNC16(QL_ + row * AROW + c16 * 16, Ql_  + gloff);
    }
    CP_COMMIT();

    auto load_kv = [&](int s, int kt) {
        const uint32_t base = KST + s * KSTAGE;
        const int k0 = kt * 64;
#pragma unroll
        for (int j = 0; j < 8; j++) {
            int id = tid + j * 128;
            int row = id >> 4, c16 = id & 15;
            size_t grow = (size_t)(b * SEQ + k0 + row) * QKV_N;
            size_t koff = grow + HID     + h * HDIM + c16 * 8;
            size_t voff = grow + 2 * HID + h * HDIM + c16 * 8;
            uint32_t d = row * AROW + c16 * 16;
            CP_ASYNC16(base + d,         QKVh + koff);
            CP_ASYNC16(base + ATILE + d, QKVh + voff);
        }
        CP_COMMIT();
    };

    load_kv(0, 0);

    const float LOG2E = 1.4426950408889634f;
    const float sscale = 0.08838834764831845f * LOG2E;
    const float slope = (h < 32) ? exp2f(-0.25f * (float)(h + 1))
                                 : exp2f(-0.125f * (float)(2 * (h - 32) + 1));
    const float slope2 = slope * LOG2E;

    const int row0 = q0 + wid * 16 + g;
    const int row1 = row0 + 8;

    float m0v = -1e30f, m1v = -1e30f, l0 = 0.f, l1 = 0.f;
    float o[16][4];
#pragma unroll
    for (int i = 0; i < 16; i++)
#pragma unroll
        for (int q = 0; q < 4; q++) o[i][q] = 0.f;

    for (int kt = 0; kt <= qt; kt++) {
        const bool more = (kt + 1 <= qt);
        if (more) load_kv((kt + 1) & 1, kt + 1);
        if (more) { CP_WAIT(1); } else { CP_WAIT(0); }
        __syncthreads();

        const uint32_t KB  = KST + (kt & 1) * KSTAGE;
        const uint32_t KHB = KB;
        const uint32_t VHB = KB + ATILE;

        float sacc[8][4];
#pragma unroll
        for (int nj = 0; nj < 8; nj++)
#pragma unroll
            for (int q = 0; q < 4; q++) sacc[nj][q] = 0.f;

#pragma unroll
        for (int dd = 0; dd < 8; dd++) {
            const uint32_t ra = (wid * 16 + lr) * AROW + dd * 32 + lc;
            uint32_t qhf[4], qlf[4];
            ldm_x4(qhf, QH_ + ra);
            ldm_x4(qlf, QL_ + ra);
            uint32_t khf[4][4];
#pragma unroll
            for (int v = 0; v < 4; v++) {
                const uint32_t rb = (v * 16 + lr) * AROW + dd * 32 + lc;
                ldm_x4(khf[v], KHB + rb);
            }
#pragma unroll
            for (int v = 0; v < 4; v++) {
                mma_f16(sacc[2*v],   qhf, khf[v][0], khf[v][2]);
                mma_f16(sacc[2*v+1], qhf, khf[v][1], khf[v][3]);
            }
#pragma unroll
            for (int v = 0; v < 4; v++) {
                mma_f16(sacc[2*v],   qlf, khf[v][0], khf[v][2]);
                mma_f16(sacc[2*v+1], qlf, khf[v][1], khf[v][3]);
            }
        }

        const int k0 = kt * 64;
        const bool diag = (kt == qt);
        float rmax0 = -1e30f, rmax1 = -1e30f;
#pragma unroll
        for (int nj = 0; nj < 8; nj++) {
#pragma unroll
            for (int e = 0; e < 2; e++) {
                const int col = k0 + nj * 8 + 2 * t + e;
                float v0 = sacc[nj][e]     * sscale + slope2 * (float)col;
                float v1 = sacc[nj][2 + e] * sscale + slope2 * (float)col;
                if (diag) {
                    if (col > row0) v0 = -1e30f;
                    if (col > row1) v1 = -1e30f;
                }
                sacc[nj][e] = v0; sacc[nj][2 + e] = v1;
                rmax0 = fmaxf(rmax0, v0); rmax1 = fmaxf(rmax1, v1);
            }
        }
        rmax0 = fmaxf(rmax0, __shfl_xor_sync(0xffffffffu, rmax0, 1));
        rmax0 = fmaxf(rmax0, __shfl_xor_sync(0xffffffffu, rmax0, 2));
        rmax1 = fmaxf(rmax1, __shfl_xor_sync(0xffffffffu, rmax1, 1));
        rmax1 = fmaxf(rmax1, __shfl_xor_sync(0xffffffffu, rmax1, 2));

        const float mn0 = fmaxf(m0v, rmax0), mn1 = fmaxf(m1v, rmax1);
        const float al0 = exp2f(m0v - mn0),  al1 = exp2f(m1v - mn1);
        m0v = mn0; m1v = mn1;

        float ps0 = 0.f, ps1 = 0.f;
#pragma unroll
        for (int nj = 0; nj < 8; nj++) {
#pragma unroll
            for (int e = 0; e < 2; e++) {
                float p0 = exp2f(sacc[nj][e]     - mn0);
                float p1 = exp2f(sacc[nj][2 + e] - mn1);
                sacc[nj][e] = p0; sacc[nj][2 + e] = p1;
                ps0 += p0; ps1 += p1;
            }
        }
        ps0 += __shfl_xor_sync(0xffffffffu, ps0, 1);
        ps0 += __shfl_xor_sync(0xffffffffu, ps0, 2);
        ps1 += __shfl_xor_sync(0xffffffffu, ps1, 1);
        ps1 += __shfl_xor_sync(0xffffffffu, ps1, 2);
        l0 = l0 * al0 + ps0;
        l1 = l1 * al1 + ps1;

#pragma unroll
        for (int i = 0; i < 16; i++) {
            o[i][0] *= al0; o[i][1] *= al0;
            o[i][2] *= al1; o[i][3] *= al1;
        }

#pragma unroll
        for (int nj = 0; nj < 8; nj++) {
#pragma unroll
            for (int rr = 0; rr < 2; rr++) {
                float x0 = sacc[nj][2*rr], x1 = sacc[nj][2*rr + 1];
                __half h0 = __float2half_rn(x0);
                __half h1 = __float2half_rn(x1);
                __half2 H; H.x = h0; H.y = h1;
                __half2 L;
                L.x = __float2half_rn(x0 - __half2float(h0));
                L.y = __float2half_rn(x1 - __half2float(h1));
                uint32_t off = (wid * 16 + g + 8 * rr) * PROW + (nj * 8 + 2 * t) * 2;
                *(__half2*)(smem + (PH_ - sb) + off) = H;
                *(__half2*)(smem + (PL_ - sb) + off) = L;
            }
        }
        __syncwarp();

#pragma unroll
        for (int ks = 0; ks < 4; ks++) {
            const uint32_t pa = (wid * 16 + lr) * PROW + ks * 32 + lc;
            uint32_t phf[4], plf[4];
            ldm_x4(phf, PH_ + pa);
            ldm_x4(plf, PL_ + pa);
#pragma unroll
            for (int nn = 0; nn < 8; nn++) {
                const uint32_t va = (ks * 16 + lr) * AROW + nn * 32 + lc;
                uint32_t vhf[4];
                ldm_x4_t(vhf, VHB + va);
                mma_f16(o[2*nn],   phf, vhf[0], vhf[1]);
                mma_f16(o[2*nn+1], phf, vhf[2], vhf[3]);
                mma_f16(o[2*nn],   plf, vhf[0], vhf[1]);
                mma_f16(o[2*nn+1], plf, vhf[2], vhf[3]);
            }
        }
        __syncthreads();
    }

    const float inv0 = 1.0f / l0, inv1 = 1.0f / l1;
#pragma unroll
    for (int i = 0; i < 16; i++) {
        const int col = h * HDIM + i * 8 + 2 * t;
#pragma unroll
        for (int rr = 0; rr < 2; rr++) {
            const float inv = rr ? inv1 : inv0;
            const int row = rr ? row1 : row0;
            float x0 = o[i][2*rr] * inv, x1 = o[i][2*rr + 1] * inv;
            __half h0 = __float2half_rn(x0);
            __half h1 = __float2half_rn(x1);
            __half2 H; H.x = h0; H.y = h1;
            __half2 L;
            L.x = __float2half_rn(x0 - __half2float(h0));
            L.y = __float2half_rn(x1 - __half2float(h1));
            size_t off = (size_t)(b * SEQ + row) * HID + col;
            *(__half2*)&Oh[off] = H;
            *(__half2*)&Ol[off] = L;
        }
    }
}

// ---------------------------------------------------------------------------
// Launch
// ---------------------------------------------------------------------------
extern "C" void kernel_launch(void* const* d_in, const int* in_sizes, int n_in,
                              void* d_out, int out_size)
{
    const float* hidden = (const float*)d_in[0];
    const float* W_pack = (const float*)d_in[1];
    const float* W_o    = (const float*)d_in[2];
    float* out = (float*)d_out;

    __half *qkvh, *qkvl, *hh, *hl, *ah, *al, *wph, *woh;
    cudaGetSymbolAddress((void**)&qkvh, g_qkvh);
    cudaGetSymbolAddress((void**)&qkvl, g_qkvl);
    cudaGetSymbolAddress((void**)&hh,  g_hh);
    cudaGetSymbolAddress((void**)&hl,  g_hl);
    cudaGetSymbolAddress((void**)&ah,  g_ah);
    cudaGetSymbolAddress((void**)&al,  g_al);
    cudaGetSymbolAddress((void**)&wph, g_wph);
    cudaGetSymbolAddress((void**)&woh, g_woh);

    cudaFuncSetAttribute(gemm_hmma, cudaFuncAttributeMaxDynamicSharedMemorySize,
                         GEMM_SMEM);
    cudaFuncSetAttribute(attn_hmma, cudaFuncAttributeMaxDynamicSharedMemorySize,
                         ATTN_SMEM);

    {
        size_t n4;
        n4 = (size_t)QKV_N * HID / 4;
        cvt_f16<<<(unsigned)((n4 + 255) / 256), 256>>>(W_pack, wph, n4);
        n4 = (size_t)HID * HID / 4;
        cvt_f16<<<(unsigned)((n4 + 255) / 256), 256>>>(W_o, woh, n4);
        n4 = (size_t)MROWS * HID / 4;
        split_f16<<<(unsigned)((n4 + 255) / 256), 256>>>(hidden, hh, hl, n4);
    }

    // GEMM1: qkv = hidden @ W_pack^T, fp16 hi out; lo only for Q columns
    gemm_hmma<<<dim3(MROWS/BM, QKV_N/BN), GTHREADS, GEMM_SMEM>>>(
        hh, hl, wph, nullptr, qkvh, qkvl, HID, MROWS, QKV_N, HID);

    // Attention (fp16 2-term flash, computed ALiBi)
    attn_hmma<<<dim3(SEQ/64, NHEAD, BATCH), 128, ATTN_SMEM>>>(qkvh, qkvl, ah, al);

    // GEMM2: out = attn @ W_o^T, fp32 out
    gemm_hmma<<<dim3(MROWS/BM, HID/BN), GTHREADS, GEMM_SMEM>>>(
        ah, al, woh, out, nullptr, nullptr, 0, MROWS, HID, HID);
}

// round 12
// speedup vs baseline: 1.1969x; 1.1969x over previous
#include <cuda_runtime.h>
#include <cuda_fp16.h>
#include <math.h>
#include <stdint.h>

// Problem constants
#define BATCH 2
#define SEQ   1024
#define HID   5120
#define NHEAD 40
#define HDIM  128
#define QKV_N (3*HID)          // 15360
#define MROWS (BATCH*SEQ)      // 2048

// ---------------------------------------------------------------------------
// Scratch (fp16)
// ---------------------------------------------------------------------------
__device__ __half g_qkvh[(size_t)MROWS * QKV_N];
__device__ __half g_qkvl[(size_t)MROWS * HID];     // lo only needed for Q region
__device__ __half g_hh[(size_t)MROWS * HID];
__device__ __half g_hl[(size_t)MROWS * HID];
__device__ __half g_ah[(size_t)MROWS * HID];
__device__ __half g_al[(size_t)MROWS * HID];
__device__ __half g_wph[(size_t)QKV_N * HID];
__device__ __half g_woh[(size_t)HID * HID];

// ---------------------------------------------------------------------------
// PTX helpers (compute_103-safe)
// ---------------------------------------------------------------------------
__device__ __forceinline__ uint32_t smem_u32(const void* p) {
    uint32_t a;
    asm("{ .reg .u64 t; cvta.to.shared.u64 t, %1; cvt.u32.u64 %0, t; }"
        : "=r"(a) : "l"(p));
    return a;
}

#define CP_ASYNC16(dst, src) \
    asm volatile("cp.async.cg.shared.global [%0], [%1], 16;" \
        :: "r"(dst), "l"(src))
#define CP_COMMIT() asm volatile("cp.async.commit_group;" ::: "memory")
#define CP_WAIT(n)  asm volatile("cp.async.wait_group %0;" :: "n"(n) : "memory")

__device__ __forceinline__ void ldm_x4(uint32_t* r, uint32_t addr) {
    asm volatile("ldmatrix.sync.aligned.m8n8.x4.shared.b16 {%0,%1,%2,%3}, [%4];"
        : "=r"(r[0]), "=r"(r[1]), "=r"(r[2]), "=r"(r[3]) : "r"(addr));
}
__device__ __forceinline__ void ldm_x4_t(uint32_t* r, uint32_t addr) {
    asm volatile("ldmatrix.sync.aligned.m8n8.x4.trans.shared.b16 {%0,%1,%2,%3}, [%4];"
        : "=r"(r[0]), "=r"(r[1]), "=r"(r[2]), "=r"(r[3]) : "r"(addr));
}

__device__ __forceinline__ void mma_f16(float* d, const uint32_t* a,
                                        uint32_t b0, uint32_t b1) {
    asm volatile(
        "mma.sync.aligned.m16n8k16.row.col.f32.f16.f16.f32 "
        "{%0,%1,%2,%3}, {%4,%5,%6,%7}, {%8,%9}, {%0,%1,%2,%3};"
        : "+f"(d[0]), "+f"(d[1]), "+f"(d[2]), "+f"(d[3])
        : "r"(a[0]), "r"(a[1]), "r"(a[2]), "r"(a[3]), "r"(b0), "r"(b1));
}

// ---------------------------------------------------------------------------
// fp32 -> fp16 hi+lo split / hi-only convert
// ---------------------------------------------------------------------------
__global__ void split_f16(const float* __restrict__ x,
                          __half* __restrict__ hi,
                          __half* __restrict__ lo, size_t n4)
{
    size_t i = (size_t)blockIdx.x * blockDim.x + threadIdx.x;
    if (i >= n4) return;
    float4 v = ((const float4*)x)[i];
    __half h0 = __float2half_rn(v.x);
    __half h1 = __float2half_rn(v.y);
    __half h2 = __float2half_rn(v.z);
    __half h3 = __float2half_rn(v.w);
    __half2 H0; H0.x = h0; H0.y = h1;
    __half2 H1; H1.x = h2; H1.y = h3;
    ((__half2*)hi)[2*i]   = H0;
    ((__half2*)hi)[2*i+1] = H1;
    __half2 L0, L1;
    L0.x = __float2half_rn(v.x - __half2float(h0));
    L0.y = __float2half_rn(v.y - __half2float(h1));
    L1.x = __float2half_rn(v.z - __half2float(h2));
    L1.y = __float2half_rn(v.w - __half2float(h3));
    ((__half2*)lo)[2*i]   = L0;
    ((__half2*)lo)[2*i+1] = L1;
}

__global__ void cvt_f16(const float* __restrict__ x,
                        __half* __restrict__ hi, size_t n4)
{
    size_t i = (size_t)blockIdx.x * blockDim.x + threadIdx.x;
    if (i >= n4) return;
    float4 v = ((const float4*)x)[i];
    __half2 H0; H0.x = __float2half_rn(v.x); H0.y = __float2half_rn(v.y);
    __half2 H1; H1.x = __float2half_rn(v.z); H1.y = __float2half_rn(v.w);
    ((__half2*)hi)[2*i]   = H0;
    ((__half2*)hi)[2*i+1] = H1;
}

// ---------------------------------------------------------------------------
// fp16 HMMA GEMM:  C = A @ B^T   (TWO_TERM: ≈ (Ah+Al)·Bh; else Ah·Bh)
// CTA 128x128, 8 warps (4M x 2N), warp tile 32x64, BK=32, 2-stage cp.async.
// B pointer is pre-offset by caller; col0/ldc place output columns globally.
// Cf != nullptr -> fp32 out; else fp16 hi out (+ lo where gcol < lo_limit).
// ---------------------------------------------------------------------------
#define BM 128
#define BN 128
#define BK 32
#define ROWB 80
#define TILEB (128 * ROWB)        // 10240
#define STAGEB (3 * TILEB)        // 30720 (Ah, Al, Bh)
#define GEMM_SMEM (2 * STAGEB)    // 61440
#define GTHREADS 256

template<bool TWO_TERM>
__global__ __launch_bounds__(GTHREADS)
void gemm_hmma(const __half* __restrict__ Ah, const __half* __restrict__ Al,
               const __half* __restrict__ Bh,
               float* __restrict__ Cf,
               __half* __restrict__ Ch, __half* __restrict__ Cl,
               int lo_limit, int col0, int ldc,
               int M, int N, int K)
{
    extern __shared__ char smem[];
    const uint32_t sbase = smem_u32(smem);
    const int tid  = threadIdx.x;
    const int wid  = tid >> 5;
    const int lane = tid & 31;
    const int wm = wid & 3;
    const int wn = wid >> 2;
    const int m0 = blockIdx.x * BM;
    const int n0 = blockIdx.y * BN;
    const int NCH = K / BK;

    // stage loader: tiles Ah(0), Al(1, only if TWO_TERM), Bh(2)
    auto load_stage = [&](int s, int kc) {
        const int k0 = kc * BK;
#pragma unroll
        for (int j = 0; j < 6; j++) {
            int id   = tid + j * GTHREADS;   // 0..1535
            int tile = id >> 9;              // 0=Ah 1=Al 2=Bh
            if (!TWO_TERM && tile == 1) continue;
            int idx  = id & 511;
            int row  = idx >> 2;
            int c16  = idx & 3;
            const __half* sb = (tile == 0) ? Ah : (tile == 1) ? Al : Bh;
            int grow = ((tile < 2) ? m0 : n0) + row;
            const void* src = sb + (size_t)grow * K + k0 + c16 * 8;
            uint32_t dst = sbase + s * STAGEB + tile * TILEB + row * ROWB + c16 * 16;
            CP_ASYNC16(dst, src);
        }
        CP_COMMIT();
    };

    float acc[2][8][4];
#pragma unroll
    for (int mi = 0; mi < 2; mi++)
#pragma unroll
        for (int nj = 0; nj < 8; nj++)
#pragma unroll
            for (int q = 0; q < 4; q++) acc[mi][nj][q] = 0.f;

    load_stage(0, 0);
    if (NCH > 1) load_stage(1, 1);

    const int lr = lane & 15;
    const int lc = (lane >> 4) * 16;
    const uint32_t rowA = (wm * 32 + lr) * ROWB + lc;
    const uint32_t rowB = (wn * 64 + lr) * ROWB + lc;

    for (int c = 0; c < NCH; c++) {
        CP_WAIT(1);
        __syncthreads();

        const uint32_t st  = sbase + (c & 1) * STAGEB;
        const uint32_t sAh = st;
        const uint32_t sAl = st + TILEB;
        const uint32_t sBh = st + 2 * TILEB;

#pragma unroll
        for (int kk = 0; kk < 2; kk++) {
            const uint32_t koff = kk * 32;
            uint32_t ahf[2][4], alf[2][4], bhf[4][4];
#pragma unroll
            for (int mi = 0; mi < 2; mi++) {
                uint32_t ra = rowA + mi * 16 * ROWB + koff;
                ldm_x4(ahf[mi], sAh + ra);
                if (TWO_TERM) ldm_x4(alf[mi], sAl + ra);
            }
#pragma unroll
            for (int nj = 0; nj < 4; nj++) {
                uint32_t rb = rowB + nj * 16 * ROWB + koff;
                ldm_x4(bhf[nj], sBh + rb);
            }
            // term 1: Ah * Bh
#pragma unroll
            for (int mi = 0; mi < 2; mi++)
#pragma unroll
                for (int nj = 0; nj < 4; nj++) {
                    mma_f16(acc[mi][2*nj],   ahf[mi], bhf[nj][0], bhf[nj][2]);
                    mma_f16(acc[mi][2*nj+1], ahf[mi], bhf[nj][1], bhf[nj][3]);
                }
            // term 2: Al * Bh
            if (TWO_TERM) {
#pragma unroll
                for (int mi = 0; mi < 2; mi++)
#pragma unroll
                    for (int nj = 0; nj < 4; nj++) {
                        mma_f16(acc[mi][2*nj],   alf[mi], bhf[nj][0], bhf[nj][2]);
                        mma_f16(acc[mi][2*nj+1], alf[mi], bhf[nj][1], bhf[nj][3]);
                    }
            }
        }

        __syncthreads();
        if (c + 2 < NCH) load_stage(c & 1, c + 2);
    }

    const int g  = lane >> 2;
    const int cc = (lane & 3) * 2;
#pragma unroll
    for (int mi = 0; mi < 2; mi++) {
        const int rbase = m0 + wm * 32 + mi * 16;
#pragma unroll
        for (int nj = 0; nj < 8; nj++) {
            const int cbase = n0 + wn * 64 + nj * 8 + cc;   // local col
            const int gcol  = col0 + cbase;                 // global col
            if (Cf) {
                float2 v0 = make_float2(acc[mi][nj][0], acc[mi][nj][1]);
                float2 v1 = make_float2(acc[mi][nj][2], acc[mi][nj][3]);
                *(float2*)&Cf[(size_t)(rbase + g) * ldc + gcol]     = v0;
                *(float2*)&Cf[(size_t)(rbase + g + 8) * ldc + gcol] = v1;
            } else {
#pragma unroll
                for (int rr = 0; rr < 2; rr++) {
                    float x0 = acc[mi][nj][2*rr], x1 = acc[mi][nj][2*rr+1];
                    __half h0 = __float2half_rn(x0);
                    __half h1 = __float2half_rn(x1);
                    __half2 H; H.x = h0; H.y = h1;
                    size_t row = (size_t)(rbase + g + 8*rr);
                    *(__half2*)&Ch[row * ldc + gcol] = H;
                    if (gcol < lo_limit) {
                        __half2 L;
                        L.x = __float2half_rn(x0 - __half2float(h0));
                        L.y = __float2half_rn(x1 - __half2float(h1));
                        *(__half2*)&Cl[row * lo_limit + gcol] = L;
                    }
                }
            }
        }
    }
}

// ---------------------------------------------------------------------------
// fp16 2-term HMMA flash attention (round 10, unchanged)
// ---------------------------------------------------------------------------
#define AROW 272
#define ATILE (64 * AROW)
#define PROW 144
#define PTILE (64 * PROW)
#define KSTAGE (2 * ATILE)
#define ATTN_SMEM (2*ATILE + 2*KSTAGE + 2*PTILE)   // 122880

__global__ __launch_bounds__(128, 1)
void attn_hmma(const __half* __restrict__ QKVh,
               const __half* __restrict__ Ql_,
               __half* __restrict__ Oh,
               __half* __restrict__ Ol)
{
    extern __shared__ char smem[];
    const uint32_t sb = smem_u32(smem);
    const int tid = threadIdx.x, wid = tid >> 5, lane = tid & 31;
    const int qt = blockIdx.x, h = blockIdx.y, b = blockIdx.z;
    const int q0 = qt * 64;
    const int lr = lane & 15, lc = (lane >> 4) * 16;
    const int g = lane >> 2, t = lane & 3;

    const uint32_t QH_ = sb, QL_ = sb + ATILE;
    const uint32_t KST = sb + 2 * ATILE;
    const uint32_t PH_ = sb + 2 * ATILE + 2 * KSTAGE;
    const uint32_t PL_ = PH_ + PTILE;

#pragma unroll
    for (int j = 0; j < 8; j++) {
        int id = tid + j * 128;
        int row = id >> 4, c16 = id & 15;
        size_t ghoff = (size_t)(b * SEQ + q0 + row) * QKV_N + h * HDIM + c16 * 8;
        size_t gloff = (size_t)(b * SEQ + q0 + row) * HID   + h * HDIM + c16 * 8;
        CP_ASYNC16(QH_ + row * AROW + c16 * 16, QKVh + ghoff);
        CP_ASYNC16(QL_ + row * AROW + c16 * 16, Ql_  + gloff);
    }
    CP_COMMIT();

    auto load_kv = [&](int s, int kt) {
        const uint32_t base = KST + s * KSTAGE;
        const int k0 = kt * 64;
#pragma unroll
        for (int j = 0; j < 8; j++) {
            int id = tid + j * 128;
            int row = id >> 4, c16 = id & 15;
            size_t grow = (size_t)(b * SEQ + k0 + row) * QKV_N;
            size_t koff = grow + HID     + h * HDIM + c16 * 8;
            size_t voff = grow + 2 * HID + h * HDIM + c16 * 8;
            uint32_t d = row * AROW + c16 * 16;
            CP_ASYNC16(base + d,         QKVh + koff);
            CP_ASYNC16(base + ATILE + d, QKVh + voff);
        }
        CP_COMMIT();
    };

    load_kv(0, 0);

    const float LOG2E = 1.4426950408889634f;
    const float sscale = 0.08838834764831845f * LOG2E;
    const float slope = (h < 32) ? exp2f(-0.25f * (float)(h + 1))
                                 : exp2f(-0.125f * (float)(2 * (h - 32) + 1));
    const float slope2 = slope * LOG2E;

    const int row0 = q0 + wid * 16 + g;
    const int row1 = row0 + 8;

    float m0v = -1e30f, m1v = -1e30f, l0 = 0.f, l1 = 0.f;
    float o[16][4];
#pragma unroll
    for (int i = 0; i < 16; i++)
#pragma unroll
        for (int q = 0; q < 4; q++) o[i][q] = 0.f;

    for (int kt = 0; kt <= qt; kt++) {
        const bool more = (kt + 1 <= qt);
        if (more) load_kv((kt + 1) & 1, kt + 1);
        if (more) { CP_WAIT(1); } else { CP_WAIT(0); }
        __syncthreads();

        const uint32_t KB  = KST + (kt & 1) * KSTAGE;
        const uint32_t KHB = KB;
        const uint32_t VHB = KB + ATILE;

        float sacc[8][4];
#pragma unroll
        for (int nj = 0; nj < 8; nj++)
#pragma unroll
            for (int q = 0; q < 4; q++) sacc[nj][q] = 0.f;

#pragma unroll
        for (int dd = 0; dd < 8; dd++) {
            const uint32_t ra = (wid * 16 + lr) * AROW + dd * 32 + lc;
            uint32_t qhf[4], qlf[4];
            ldm_x4(qhf, QH_ + ra);
            ldm_x4(qlf, QL_ + ra);
            uint32_t khf[4][4];
#pragma unroll
            for (int v = 0; v < 4; v++) {
                const uint32_t rb = (v * 16 + lr) * AROW + dd * 32 + lc;
                ldm_x4(khf[v], KHB + rb);
            }
#pragma unroll
            for (int v = 0; v < 4; v++) {
                mma_f16(sacc[2*v],   qhf, khf[v][0], khf[v][2]);
                mma_f16(sacc[2*v+1], qhf, khf[v][1], khf[v][3]);
            }
#pragma unroll
            for (int v = 0; v < 4; v++) {
                mma_f16(sacc[2*v],   qlf, khf[v][0], khf[v][2]);
                mma_f16(sacc[2*v+1], qlf, khf[v][1], khf[v][3]);
            }
        }

        const int k0 = kt * 64;
        const bool diag = (kt == qt);
        float rmax0 = -1e30f, rmax1 = -1e30f;
#pragma unroll
        for (int nj = 0; nj < 8; nj++) {
#pragma unroll
            for (int e = 0; e < 2; e++) {
                const int col = k0 + nj * 8 + 2 * t + e;
                float v0 = sacc[nj][e]     * sscale + slope2 * (float)col;
                float v1 = sacc[nj][2 + e] * sscale + slope2 * (float)col;
                if (diag) {
                    if (col > row0) v0 = -1e30f;
                    if (col > row1) v1 = -1e30f;
                }
                sacc[nj][e] = v0; sacc[nj][2 + e] = v1;
                rmax0 = fmaxf(rmax0, v0); rmax1 = fmaxf(rmax1, v1);
            }
        }
        rmax0 = fmaxf(rmax0, __shfl_xor_sync(0xffffffffu, rmax0, 1));
        rmax0 = fmaxf(rmax0, __shfl_xor_sync(0xffffffffu, rmax0, 2));
        rmax1 = fmaxf(rmax1, __shfl_xor_sync(0xffffffffu, rmax1, 1));
        rmax1 = fmaxf(rmax1, __shfl_xor_sync(0xffffffffu, rmax1, 2));

        const float mn0 = fmaxf(m0v, rmax0), mn1 = fmaxf(m1v, rmax1);
        const float al0 = exp2f(m0v - mn0),  al1 = exp2f(m1v - mn1);
        m0v = mn0; m1v = mn1;

        float ps0 = 0.f, ps1 = 0.f;
#pragma unroll
        for (int nj = 0; nj < 8; nj++) {
#pragma unroll
            for (int e = 0; e < 2; e++) {
                float p0 = exp2f(sacc[nj][e]     - mn0);
                float p1 = exp2f(sacc[nj][2 + e] - mn1);
                sacc[nj][e] = p0; sacc[nj][2 + e] = p1;
                ps0 += p0; ps1 += p1;
            }
        }
        ps0 += __shfl_xor_sync(0xffffffffu, ps0, 1);
        ps0 += __shfl_xor_sync(0xffffffffu, ps0, 2);
        ps1 += __shfl_xor_sync(0xffffffffu, ps1, 1);
        ps1 += __shfl_xor_sync(0xffffffffu, ps1, 2);
        l0 = l0 * al0 + ps0;
        l1 = l1 * al1 + ps1;

#pragma unroll
        for (int i = 0; i < 16; i++) {
            o[i][0] *= al0; o[i][1] *= al0;
            o[i][2] *= al1; o[i][3] *= al1;
        }

#pragma unroll
        for (int nj = 0; nj < 8; nj++) {
#pragma unroll
            for (int rr = 0; rr < 2; rr++) {
                float x0 = sacc[nj][2*rr], x1 = sacc[nj][2*rr + 1];
                __half h0 = __float2half_rn(x0);
                __half h1 = __float2half_rn(x1);
                __half2 H; H.x = h0; H.y = h1;
                __half2 L;
                L.x = __float2half_rn(x0 - __half2float(h0));
                L.y = __float2half_rn(x1 - __half2float(h1));
                uint32_t off = (wid * 16 + g + 8 * rr) * PROW + (nj * 8 + 2 * t) * 2;
                *(__half2*)(smem + (PH_ - sb) + off) = H;
                *(__half2*)(smem + (PL_ - sb) + off) = L;
            }
        }
        __syncwarp();

#pragma unroll
        for (int ks = 0; ks < 4; ks++) {
            const uint32_t pa = (wid * 16 + lr) * PROW + ks * 32 + lc;
            uint32_t phf[4], plf[4];
            ldm_x4(phf, PH_ + pa);
            ldm_x4(plf, PL_ + pa);
#pragma unroll
            for (int nn = 0; nn < 8; nn++) {
                const uint32_t va = (ks * 16 + lr) * AROW + nn * 32 + lc;
                uint32_t vhf[4];
                ldm_x4_t(vhf, VHB + va);
                mma_f16(o[2*nn],   phf, vhf[0], vhf[1]);
                mma_f16(o[2*nn+1], phf, vhf[2], vhf[3]);
                mma_f16(o[2*nn],   plf, vhf[0], vhf[1]);
                mma_f16(o[2*nn+1], plf, vhf[2], vhf[3]);
            }
        }
        __syncthreads();
    }

    const float inv0 = 1.0f / l0, inv1 = 1.0f / l1;
#pragma unroll
    for (int i = 0; i < 16; i++) {
        const int col = h * HDIM + i * 8 + 2 * t;
#pragma unroll
        for (int rr = 0; rr < 2; rr++) {
            const float inv = rr ? inv1 : inv0;
            const int row = rr ? row1 : row0;
            float x0 = o[i][2*rr] * inv, x1 = o[i][2*rr + 1] * inv;
            __half h0 = __float2half_rn(x0);
            __half h1 = __float2half_rn(x1);
            __half2 H; H.x = h0; H.y = h1;
            __half2 L;
            L.x = __float2half_rn(x0 - __half2float(h0));
            L.y = __float2half_rn(x1 - __half2float(h1));
            size_t off = (size_t)(b * SEQ + row) * HID + col;
            *(__half2*)&Oh[off] = H;
            *(__half2*)&Ol[off] = L;
        }
    }
}

// ---------------------------------------------------------------------------
// Launch
// ---------------------------------------------------------------------------
extern "C" void kernel_launch(void* const* d_in, const int* in_sizes, int n_in,
                              void* d_out, int out_size)
{
    const float* hidden = (const float*)d_in[0];
    const float* W_pack = (const float*)d_in[1];
    const float* W_o    = (const float*)d_in[2];
    float* out = (float*)d_out;

    __half *qkvh, *qkvl, *hh, *hl, *ah, *al, *wph, *woh;
    cudaGetSymbolAddress((void**)&qkvh, g_qkvh);
    cudaGetSymbolAddress((void**)&qkvl, g_qkvl);
    cudaGetSymbolAddress((void**)&hh,  g_hh);
    cudaGetSymbolAddress((void**)&hl,  g_hl);
    cudaGetSymbolAddress((void**)&ah,  g_ah);
    cudaGetSymbolAddress((void**)&al,  g_al);
    cudaGetSymbolAddress((void**)&wph, g_wph);
    cudaGetSymbolAddress((void**)&woh, g_woh);

    cudaFuncSetAttribute(gemm_hmma<true>,
                         cudaFuncAttributeMaxDynamicSharedMemorySize, GEMM_SMEM);
    cudaFuncSetAttribute(gemm_hmma<false>,
                         cudaFuncAttributeMaxDynamicSharedMemorySize, GEMM_SMEM);
    cudaFuncSetAttribute(attn_hmma,
                         cudaFuncAttributeMaxDynamicSharedMemorySize, ATTN_SMEM);

    {
        size_t n4;
        n4 = (size_t)QKV_N * HID / 4;
        cvt_f16<<<(unsigned)((n4 + 255) / 256), 256>>>(W_pack, wph, n4);
        n4 = (size_t)HID * HID / 4;
        cvt_f16<<<(unsigned)((n4 + 255) / 256), 256>>>(W_o, woh, n4);
        n4 = (size_t)MROWS * HID / 4;
        split_f16<<<(unsigned)((n4 + 255) / 256), 256>>>(hidden, hh, hl, n4);
    }

    // GEMM1a: Q columns [0, 5120), 2-term (feeds Q hi+lo)
    gemm_hmma<true><<<dim3(MROWS/BM, HID/BN), GTHREADS, GEMM_SMEM>>>(
        hh, hl, wph, nullptr, qkvh, qkvl,
        /*lo_limit=*/HID, /*col0=*/0, /*ldc=*/QKV_N,
        MROWS, HID, HID);

    // GEMM1b: K,V columns [5120, 15360), 1-term (outputs rounded to fp16 anyway)
    gemm_hmma<false><<<dim3(MROWS/BM, (QKV_N-HID)/BN), GTHREADS, GEMM_SMEM>>>(
        hh, hl, wph + (size_t)HID * HID, nullptr, qkvh, qkvl,
        /*lo_limit=*/0, /*col0=*/HID, /*ldc=*/QKV_N,
        MROWS, QKV_N - HID, HID);

    // Attention (fp16 2-term flash, computed ALiBi)
    attn_hmma<<<dim3(SEQ/64, NHEAD, BATCH), 128, ATTN_SMEM>>>(qkvh, qkvl, ah, al);

    // GEMM2: out = attn @ W_o^T, 2-term, fp32 out
    gemm_hmma<true><<<dim3(MROWS/BM, HID/BN), GTHREADS, GEMM_SMEM>>>(
        ah, al, woh, out, nullptr, nullptr,
        /*lo_limit=*/0, /*col0=*/0, /*ldc=*/HID,
        MROWS, HID, HID);
}

// round 13
// speedup vs baseline: 1.3853x; 1.1574x over previous
#include <cuda_runtime.h>
#include <cuda_fp16.h>
#include <math.h>
#include <stdint.h>

// Problem constants
#define BATCH 2
#define SEQ   1024
#define HID   5120
#define NHEAD 40
#define HDIM  128
#define QKV_N (3*HID)          // 15360
#define MROWS (BATCH*SEQ)      // 2048

// ---------------------------------------------------------------------------
// Scratch (fp16)
// ---------------------------------------------------------------------------
__device__ __half g_qkvh[(size_t)MROWS * QKV_N];
__device__ __half g_qkvl[(size_t)MROWS * HID];     // lo only needed for Q region
__device__ __half g_hh[(size_t)MROWS * HID];
__device__ __half g_hl[(size_t)MROWS * HID];
__device__ __half g_ah[(size_t)MROWS * HID];
__device__ __half g_wph[(size_t)QKV_N * HID];
__device__ __half g_woh[(size_t)HID * HID];

// ---------------------------------------------------------------------------
// PTX helpers (compute_103-safe)
// ---------------------------------------------------------------------------
__device__ __forceinline__ uint32_t smem_u32(const void* p) {
    uint32_t a;
    asm("{ .reg .u64 t; cvta.to.shared.u64 t, %1; cvt.u32.u64 %0, t; }"
        : "=r"(a) : "l"(p));
    return a;
}

#define CP_ASYNC16(dst, src) \
    asm volatile("cp.async.cg.shared.global [%0], [%1], 16;" \
        :: "r"(dst), "l"(src))
#define CP_COMMIT() asm volatile("cp.async.commit_group;" ::: "memory")
#define CP_WAIT(n)  asm volatile("cp.async.wait_group %0;" :: "n"(n) : "memory")

__device__ __forceinline__ void ldm_x4(uint32_t* r, uint32_t addr) {
    asm volatile("ldmatrix.sync.aligned.m8n8.x4.shared.b16 {%0,%1,%2,%3}, [%4];"
        : "=r"(r[0]), "=r"(r[1]), "=r"(r[2]), "=r"(r[3]) : "r"(addr));
}
__device__ __forceinline__ void ldm_x4_t(uint32_t* r, uint32_t addr) {
    asm volatile("ldmatrix.sync.aligned.m8n8.x4.trans.shared.b16 {%0,%1,%2,%3}, [%4];"
        : "=r"(r[0]), "=r"(r[1]), "=r"(r[2]), "=r"(r[3]) : "r"(addr));
}

__device__ __forceinline__ void mma_f16(float* d, const uint32_t* a,
                                        uint32_t b0, uint32_t b1) {
    asm volatile(
        "mma.sync.aligned.m16n8k16.row.col.f32.f16.f16.f32 "
        "{%0,%1,%2,%3}, {%4,%5,%6,%7}, {%8,%9}, {%0,%1,%2,%3};"
        : "+f"(d[0]), "+f"(d[1]), "+f"(d[2]), "+f"(d[3])
        : "r"(a[0]), "r"(a[1]), "r"(a[2]), "r"(a[3]), "r"(b0), "r"(b1));
}

// ---------------------------------------------------------------------------
// fp32 -> fp16 hi+lo split / hi-only convert
// ---------------------------------------------------------------------------
__global__ void split_f16(const float* __restrict__ x,
                          __half* __restrict__ hi,
                          __half* __restrict__ lo, size_t n4)
{
    size_t i = (size_t)blockIdx.x * blockDim.x + threadIdx.x;
    if (i >= n4) return;
    float4 v = ((const float4*)x)[i];
    __half h0 = __float2half_rn(v.x);
    __half h1 = __float2half_rn(v.y);
    __half h2 = __float2half_rn(v.z);
    __half h3 = __float2half_rn(v.w);
    __half2 H0; H0.x = h0; H0.y = h1;
    __half2 H1; H1.x = h2; H1.y = h3;
    ((__half2*)hi)[2*i]   = H0;
    ((__half2*)hi)[2*i+1] = H1;
    __half2 L0, L1;
    L0.x = __float2half_rn(v.x - __half2float(h0));
    L0.y = __float2half_rn(v.y - __half2float(h1));
    L1.x = __float2half_rn(v.z - __half2float(h2));
    L1.y = __float2half_rn(v.w - __half2float(h3));
    ((__half2*)lo)[2*i]   = L0;
    ((__half2*)lo)[2*i+1] = L1;
}

__global__ void cvt_f16(const float* __restrict__ x,
                        __half* __restrict__ hi, size_t n4)
{
    size_t i = (size_t)blockIdx.x * blockDim.x + threadIdx.x;
    if (i >= n4) return;
    float4 v = ((const float4*)x)[i];
    __half2 H0; H0.x = __float2half_rn(v.x); H0.y = __float2half_rn(v.y);
    __half2 H1; H1.x = __float2half_rn(v.z); H1.y = __float2half_rn(v.w);
    ((__half2*)hi)[2*i]   = H0;
    ((__half2*)hi)[2*i+1] = H1;
}

// ---------------------------------------------------------------------------
// fp16 HMMA GEMM:  C = A @ B^T
// Per-CTA runtime precision: blockIdx.y < two_term_bn -> (Ah+Al)·Bh, else Ah·Bh.
// CTA 128x128, 8 warps (4M x 2N), warp tile 32x64, BK=32, 2-stage cp.async.
// Cf != nullptr -> fp32 out; else fp16 hi out (+ lo where gcol < lo_limit).
// ---------------------------------------------------------------------------
#define BM 128
#define BN 128
#define BK 32
#define ROWB 80
#define TILEB (128 * ROWB)        // 10240
#define STAGEB (3 * TILEB)        // 30720 (Ah, Al, Bh)
#define GEMM_SMEM (2 * STAGEB)    // 61440
#define GTHREADS 256

__global__ __launch_bounds__(GTHREADS)
void gemm_hmma(const __half* __restrict__ Ah, const __half* __restrict__ Al,
               const __half* __restrict__ Bh,
               float* __restrict__ Cf,
               __half* __restrict__ Ch, __half* __restrict__ Cl,
               int lo_limit, int two_term_bn, int ldc,
               int M, int N, int K)
{
    extern __shared__ char smem[];
    const uint32_t sbase = smem_u32(smem);
    const int tid  = threadIdx.x;
    const int wid  = tid >> 5;
    const int lane = tid & 31;
    const int wm = wid & 3;
    const int wn = wid >> 2;
    const int m0 = blockIdx.x * BM;
    const int n0 = blockIdx.y * BN;
    const int NCH = K / BK;
    const bool two_term = (int)blockIdx.y < two_term_bn;

    // stage loader: tiles Ah(0), Al(1, only if two_term), Bh(2)
    auto load_stage = [&](int s, int kc) {
        const int k0 = kc * BK;
#pragma unroll
        for (int j = 0; j < 6; j++) {
            int id   = tid + j * GTHREADS;   // 0..1535
            int tile = id >> 9;              // 0=Ah 1=Al 2=Bh
            if (tile == 1 && !two_term) continue;
            int idx  = id & 511;
            int row  = idx >> 2;
            int c16  = idx & 3;
            const __half* sb = (tile == 0) ? Ah : (tile == 1) ? Al : Bh;
            int grow = ((tile < 2) ? m0 : n0) + row;
            const void* src = sb + (size_t)grow * K + k0 + c16 * 8;
            uint32_t dst = sbase + s * STAGEB + tile * TILEB + row * ROWB + c16 * 16;
            CP_ASYNC16(dst, src);
        }
        CP_COMMIT();
    };

    float acc[2][8][4];
#pragma unroll
    for (int mi = 0; mi < 2; mi++)
#pragma unroll
        for (int nj = 0; nj < 8; nj++)
#pragma unroll
            for (int q = 0; q < 4; q++) acc[mi][nj][q] = 0.f;

    load_stage(0, 0);
    if (NCH > 1) load_stage(1, 1);

    const int lr = lane & 15;
    const int lc = (lane >> 4) * 16;
    const uint32_t rowA = (wm * 32 + lr) * ROWB + lc;
    const uint32_t rowB = (wn * 64 + lr) * ROWB + lc;

    for (int c = 0; c < NCH; c++) {
        CP_WAIT(1);
        __syncthreads();

        const uint32_t st  = sbase + (c & 1) * STAGEB;
        const uint32_t sAh = st;
        const uint32_t sAl = st + TILEB;
        const uint32_t sBh = st + 2 * TILEB;

#pragma unroll
        for (int kk = 0; kk < 2; kk++) {
            const uint32_t koff = kk * 32;
            uint32_t ahf[2][4], bhf[4][4];
#pragma unroll
            for (int mi = 0; mi < 2; mi++) {
                uint32_t ra = rowA + mi * 16 * ROWB + koff;
                ldm_x4(ahf[mi], sAh + ra);
            }
#pragma unroll
            for (int nj = 0; nj < 4; nj++) {
                uint32_t rb = rowB + nj * 16 * ROWB + koff;
                ldm_x4(bhf[nj], sBh + rb);
            }
            // term 1: Ah * Bh
#pragma unroll
            for (int mi = 0; mi < 2; mi++)
#pragma unroll
                for (int nj = 0; nj < 4; nj++) {
                    mma_f16(acc[mi][2*nj],   ahf[mi], bhf[nj][0], bhf[nj][2]);
                    mma_f16(acc[mi][2*nj+1], ahf[mi], bhf[nj][1], bhf[nj][3]);
                }
            // term 2: Al * Bh (uniform branch; only for two_term CTAs)
            if (two_term) {
                uint32_t alf[2][4];
#pragma unroll
                for (int mi = 0; mi < 2; mi++) {
                    uint32_t ra = rowA + mi * 16 * ROWB + koff;
                    ldm_x4(alf[mi], sAl + ra);
                }
#pragma unroll
                for (int mi = 0; mi < 2; mi++)
#pragma unroll
                    for (int nj = 0; nj < 4; nj++) {
                        mma_f16(acc[mi][2*nj],   alf[mi], bhf[nj][0], bhf[nj][2]);
                        mma_f16(acc[mi][2*nj+1], alf[mi], bhf[nj][1], bhf[nj][3]);
                    }
            }
        }

        __syncthreads();
        if (c + 2 < NCH) load_stage(c & 1, c + 2);
    }

    const int g  = lane >> 2;
    const int cc = (lane & 3) * 2;
#pragma unroll
    for (int mi = 0; mi < 2; mi++) {
        const int rbase = m0 + wm * 32 + mi * 16;
#pragma unroll
        for (int nj = 0; nj < 8; nj++) {
            const int gcol = n0 + wn * 64 + nj * 8 + cc;
            if (Cf) {
                float2 v0 = make_float2(acc[mi][nj][0], acc[mi][nj][1]);
                float2 v1 = make_float2(acc[mi][nj][2], acc[mi][nj][3]);
                *(float2*)&Cf[(size_t)(rbase + g) * ldc + gcol]     = v0;
                *(float2*)&Cf[(size_t)(rbase + g + 8) * ldc + gcol] = v1;
            } else {
#pragma unroll
                for (int rr = 0; rr < 2; rr++) {
                    float x0 = acc[mi][nj][2*rr], x1 = acc[mi][nj][2*rr+1];
                    __half h0 = __float2half_rn(x0);
                    __half h1 = __float2half_rn(x1);
                    __half2 H; H.x = h0; H.y = h1;
                    size_t row = (size_t)(rbase + g + 8*rr);
                    *(__half2*)&Ch[row * ldc + gcol] = H;
                    if (gcol < lo_limit) {
                        __half2 L;
                        L.x = __float2half_rn(x0 - __half2float(h0));
                        L.y = __float2half_rn(x1 - __half2float(h1));
                        *(__half2*)&Cl[row * lo_limit + gcol] = L;
                    }
                }
            }
        }
    }
}

// ---------------------------------------------------------------------------
// fp16 2-term HMMA flash attention; writes hi-only output (GEMM2 is 1-term)
// ---------------------------------------------------------------------------
#define AROW 272
#define ATILE (64 * AROW)
#define PROW 144
#define PTILE (64 * PROW)
#define KSTAGE (2 * ATILE)
#define ATTN_SMEM (2*ATILE + 2*KSTAGE + 2*PTILE)   // 122880

__global__ __launch_bounds__(128, 1)
void attn_hmma(const __half* __restrict__ QKVh,
               const __half* __restrict__ Ql_,
               __half* __restrict__ Oh)
{
    extern __shared__ char smem[];
    const uint32_t sb = smem_u32(smem);
    const int tid = threadIdx.x, wid = tid >> 5, lane = tid & 31;
    const int qt = blockIdx.x, h = blockIdx.y, b = blockIdx.z;
    const int q0 = qt * 64;
    const int lr = lane & 15, lc = (lane >> 4) * 16;
    const int g = lane >> 2, t = lane & 3;

    const uint32_t QH_ = sb, QL_ = sb + ATILE;
    const uint32_t KST = sb + 2 * ATILE;
    const uint32_t PH_ = sb + 2 * ATILE + 2 * KSTAGE;
    const uint32_t PL_ = PH_ + PTILE;

#pragma unroll
    for (int j = 0; j < 8; j++) {
        int id = tid + j * 128;
        int row = id >> 4, c16 = id & 15;
        size_t ghoff = (size_t)(b * SEQ + q0 + row) * QKV_N + h * HDIM + c16 * 8;
        size_t gloff = (size_t)(b * SEQ + q0 + row) * HID   + h * HDIM + c16 * 8;
        CP_ASYNC16(QH_ + row * AROW + c16 * 16, QKVh + ghoff);
        CP_ASYNC16(QL_ + row * AROW + c16 * 16, Ql_  + gloff);
    }
    CP_COMMIT();

    auto load_kv = [&](int s, int kt) {
        const uint32_t base = KST + s * KSTAGE;
        const int k0 = kt * 64;
#pragma unroll
        for (int j = 0; j < 8; j++) {
            int id = tid + j * 128;
            int row = id >> 4, c16 = id & 15;
            size_t grow = (size_t)(b * SEQ + k0 + row) * QKV_N;
            size_t koff = grow + HID     + h * HDIM + c16 * 8;
            size_t voff = grow + 2 * HID + h * HDIM + c16 * 8;
            uint32_t d = row * AROW + c16 * 16;
            CP_ASYNC16(base + d,         QKVh + koff);
            CP_ASYNC16(base + ATILE + d, QKVh + voff);
        }
        CP_COMMIT();
    };

    load_kv(0, 0);

    const float LOG2E = 1.4426950408889634f;
    const float sscale = 0.08838834764831845f * LOG2E;
    const float slope = (h < 32) ? exp2f(-0.25f * (float)(h + 1))
                                 : exp2f(-0.125f * (float)(2 * (h - 32) + 1));
    const float slope2 = slope * LOG2E;

    const int row0 = q0 + wid * 16 + g;
    const int row1 = row0 + 8;

    float m0v = -1e30f, m1v = -1e30f, l0 = 0.f, l1 = 0.f;
    float o[16][4];
#pragma unroll
    for (int i = 0; i < 16; i++)
#pragma unroll
        for (int q = 0; q < 4; q++) o[i][q] = 0.f;

    for (int kt = 0; kt <= qt; kt++) {
        const bool more = (kt + 1 <= qt);
        if (more) load_kv((kt + 1) & 1, kt + 1);
        if (more) { CP_WAIT(1); } else { CP_WAIT(0); }
        __syncthreads();

        const uint32_t KB  = KST + (kt & 1) * KSTAGE;
        const uint32_t KHB = KB;
        const uint32_t VHB = KB + ATILE;

        float sacc[8][4];
#pragma unroll
        for (int nj = 0; nj < 8; nj++)
#pragma unroll
            for (int q = 0; q < 4; q++) sacc[nj][q] = 0.f;

#pragma unroll
        for (int dd = 0; dd < 8; dd++) {
            const uint32_t ra = (wid * 16 + lr) * AROW + dd * 32 + lc;
            uint32_t qhf[4], qlf[4];
            ldm_x4(qhf, QH_ + ra);
            ldm_x4(qlf, QL_ + ra);
            uint32_t khf[4][4];
#pragma unroll
            for (int v = 0; v < 4; v++) {
                const uint32_t rb = (v * 16 + lr) * AROW + dd * 32 + lc;
                ldm_x4(khf[v], KHB + rb);
            }
#pragma unroll
            for (int v = 0; v < 4; v++) {
                mma_f16(sacc[2*v],   qhf, khf[v][0], khf[v][2]);
                mma_f16(sacc[2*v+1], qhf, khf[v][1], khf[v][3]);
            }
#pragma unroll
            for (int v = 0; v < 4; v++) {
                mma_f16(sacc[2*v],   qlf, khf[v][0], khf[v][2]);
                mma_f16(sacc[2*v+1], qlf, khf[v][1], khf[v][3]);
            }
        }

        const int k0 = kt * 64;
        const bool diag = (kt == qt);
        float rmax0 = -1e30f, rmax1 = -1e30f;
#pragma unroll
        for (int nj = 0; nj < 8; nj++) {
#pragma unroll
            for (int e = 0; e < 2; e++) {
                const int col = k0 + nj * 8 + 2 * t + e;
                float v0 = sacc[nj][e]     * sscale + slope2 * (float)col;
                float v1 = sacc[nj][2 + e] * sscale + slope2 * (float)col;
                if (diag) {
                    if (col > row0) v0 = -1e30f;
                    if (col > row1) v1 = -1e30f;
                }
                sacc[nj][e] = v0; sacc[nj][2 + e] = v1;
                rmax0 = fmaxf(rmax0, v0); rmax1 = fmaxf(rmax1, v1);
            }
        }
        rmax0 = fmaxf(rmax0, __shfl_xor_sync(0xffffffffu, rmax0, 1));
        rmax0 = fmaxf(rmax0, __shfl_xor_sync(0xffffffffu, rmax0, 2));
        rmax1 = fmaxf(rmax1, __shfl_xor_sync(0xffffffffu, rmax1, 1));
        rmax1 = fmaxf(rmax1, __shfl_xor_sync(0xffffffffu, rmax1, 2));

        const float mn0 = fmaxf(m0v, rmax0), mn1 = fmaxf(m1v, rmax1);
        const float al0 = exp2f(m0v - mn0),  al1 = exp2f(m1v - mn1);
        m0v = mn0; m1v = mn1;

        float ps0 = 0.f, ps1 = 0.f;
#pragma unroll
        for (int nj = 0; nj < 8; nj++) {
#pragma unroll
            for (int e = 0; e < 2; e++) {
                float p0 = exp2f(sacc[nj][e]     - mn0);
                float p1 = exp2f(sacc[nj][2 + e] - mn1);
                sacc[nj][e] = p0; sacc[nj][2 + e] = p1;
                ps0 += p0; ps1 += p1;
            }
        }
        ps0 += __shfl_xor_sync(0xffffffffu, ps0, 1);
        ps0 += __shfl_xor_sync(0xffffffffu, ps0, 2);
        ps1 += __shfl_xor_sync(0xffffffffu, ps1, 1);
        ps1 += __shfl_xor_sync(0xffffffffu, ps1, 2);
        l0 = l0 * al0 + ps0;
        l1 = l1 * al1 + ps1;

#pragma unroll
        for (int i = 0; i < 16; i++) {
            o[i][0] *= al0; o[i][1] *= al0;
            o[i][2] *= al1; o[i][3] *= al1;
        }

#pragma unroll
        for (int nj = 0; nj < 8; nj++) {
#pragma unroll
            for (int rr = 0; rr < 2; rr++) {
                float x0 = sacc[nj][2*rr], x1 = sacc[nj][2*rr + 1];
                __half h0 = __float2half_rn(x0);
                __half h1 = __float2half_rn(x1);
                __half2 H; H.x = h0; H.y = h1;
                __half2 L;
                L.x = __float2half_rn(x0 - __half2float(h0));
                L.y = __float2half_rn(x1 - __half2float(h1));
                uint32_t off = (wid * 16 + g + 8 * rr) * PROW + (nj * 8 + 2 * t) * 2;
                *(__half2*)(smem + (PH_ - sb) + off) = H;
                *(__half2*)(smem + (PL_ - sb) + off) = L;
            }
        }
        __syncwarp();

#pragma unroll
        for (int ks = 0; ks < 4; ks++) {
            const uint32_t pa = (wid * 16 + lr) * PROW + ks * 32 + lc;
            uint32_t phf[4], plf[4];
            ldm_x4(phf, PH_ + pa);
            ldm_x4(plf, PL_ + pa);
#pragma unroll
            for (int nn = 0; nn < 8; nn++) {
                const uint32_t va = (ks * 16 + lr) * AROW + nn * 32 + lc;
                uint32_t vhf[4];
                ldm_x4_t(vhf, VHB + va);
                mma_f16(o[2*nn],   phf, vhf[0], vhf[1]);
                mma_f16(o[2*nn+1], phf, vhf[2], vhf[3]);
                mma_f16(o[2*nn],   plf, vhf[0], vhf[1]);
                mma_f16(o[2*nn+1], plf, vhf[2], vhf[3]);
            }
        }
        __syncthreads();
    }

    // epilogue: normalize, hi-only fp16 output (GEMM2 consumes 1-term)
    const float inv0 = 1.0f / l0, inv1 = 1.0f / l1;
#pragma unroll
    for (int i = 0; i < 16; i++) {
        const int col = h * HDIM + i * 8 + 2 * t;
#pragma unroll
        for (int rr = 0; rr < 2; rr++) {
            const float inv = rr ? inv1 : inv0;
            const int row = rr ? row1 : row0;
            float x0 = o[i][2*rr] * inv, x1 = o[i][2*rr + 1] * inv;
            __half2 H; H.x = __float2half_rn(x0); H.y = __float2half_rn(x1);
            *(__half2*)&Oh[(size_t)(b * SEQ + row) * HID + col] = H;
        }
    }
}

// ---------------------------------------------------------------------------
// Launch
// ---------------------------------------------------------------------------
extern "C" void kernel_launch(void* const* d_in, const int* in_sizes, int n_in,
                              void* d_out, int out_size)
{
    const float* hidden = (const float*)d_in[0];
    const float* W_pack = (const float*)d_in[1];
    const float* W_o    = (const float*)d_in[2];
    float* out = (float*)d_out;

    __half *qkvh, *qkvl, *hh, *hl, *ah, *wph, *woh;
    cudaGetSymbolAddress((void**)&qkvh, g_qkvh);
    cudaGetSymbolAddress((void**)&qkvl, g_qkvl);
    cudaGetSymbolAddress((void**)&hh,  g_hh);
    cudaGetSymbolAddress((void**)&hl,  g_hl);
    cudaGetSymbolAddress((void**)&ah,  g_ah);
    cudaGetSymbolAddress((void**)&wph, g_wph);
    cudaGetSymbolAddress((void**)&woh, g_woh);

    cudaFuncSetAttribute(gemm_hmma,
                         cudaFuncAttributeMaxDynamicSharedMemorySize, GEMM_SMEM);
    cudaFuncSetAttribute(attn_hmma,
                         cudaFuncAttributeMaxDynamicSharedMemorySize, ATTN_SMEM);

    {
        size_t n4;
        n4 = (size_t)QKV_N * HID / 4;
        cvt_f16<<<(unsigned)((n4 + 255) / 256), 256>>>(W_pack, wph, n4);
        n4 = (size_t)HID * HID / 4;
        cvt_f16<<<(unsigned)((n4 + 255) / 256), 256>>>(W_o, woh, n4);
        n4 = (size_t)MROWS * HID / 4;
        split_f16<<<(unsigned)((n4 + 255) / 256), 256>>>(hidden, hh, hl, n4);
    }

    // GEMM1 (fused): qkv = hidden @ W_pack^T.
    // Q columns (blockIdx.y < 40): 2-term, hi+lo out. K/V columns: 1-term, hi out.
    gemm_hmma<<<dim3(MROWS/BM, QKV_N/BN), GTHREADS, GEMM_SMEM>>>(
        hh, hl, wph, nullptr, qkvh, qkvl,
        /*lo_limit=*/HID, /*two_term_bn=*/HID/BN, /*ldc=*/QKV_N,
        MROWS, QKV_N, HID);

    // Attention (fp16 2-term flash, computed ALiBi); hi-only output
    attn_hmma<<<dim3(SEQ/64, NHEAD, BATCH), 128, ATTN_SMEM>>>(qkvh, qkvl, ah);

    // GEMM2: out = attn @ W_o^T, 1-term (A is fp16-rounded anyway), fp32 out
    gemm_hmma<<<dim3(MROWS/BM, HID/BN), GTHREADS, GEMM_SMEM>>>(
        ah, nullptr, woh, out, nullptr, nullptr,
        /*lo_limit=*/0, /*two_term_bn=*/0, /*ldc=*/HID,
        MROWS, HID, HID);
}

// round 14
// speedup vs baseline: 1.4162x; 1.0223x over previous
#include <cuda_runtime.h>
#include <cuda_fp16.h>
#include <math.h>
#include <stdint.h>

// Problem constants
#define BATCH 2
#define SEQ   1024
#define HID   5120
#define NHEAD 40
#define HDIM  128
#define QKV_N (3*HID)          // 15360
#define MROWS (BATCH*SEQ)      // 2048

// ---------------------------------------------------------------------------
// Scratch (fp16)
// ---------------------------------------------------------------------------
__device__ __half g_qkvh[(size_t)MROWS * QKV_N];
__device__ __half g_qkvl[(size_t)MROWS * HID];     // lo only needed for Q region
__device__ __half g_hh[(size_t)MROWS * HID];
__device__ __half g_hl[(size_t)MROWS * HID];
__device__ __half g_ah[(size_t)MROWS * HID];
__device__ __half g_wph[(size_t)QKV_N * HID];
__device__ __half g_woh[(size_t)HID * HID];

// ---------------------------------------------------------------------------
// PTX helpers (compute_103-safe)
// ---------------------------------------------------------------------------
__device__ __forceinline__ uint32_t smem_u32(const void* p) {
    uint32_t a;
    asm("{ .reg .u64 t; cvta.to.shared.u64 t, %1; cvt.u32.u64 %0, t; }"
        : "=r"(a) : "l"(p));
    return a;
}

#define CP_ASYNC16(dst, src) \
    asm volatile("cp.async.cg.shared.global [%0], [%1], 16;" \
        :: "r"(dst), "l"(src))
#define CP_COMMIT() asm volatile("cp.async.commit_group;" ::: "memory")
#define CP_WAIT(n)  asm volatile("cp.async.wait_group %0;" :: "n"(n) : "memory")

__device__ __forceinline__ void ldm_x4(uint32_t* r, uint32_t addr) {
    asm volatile("ldmatrix.sync.aligned.m8n8.x4.shared.b16 {%0,%1,%2,%3}, [%4];"
        : "=r"(r[0]), "=r"(r[1]), "=r"(r[2]), "=r"(r[3]) : "r"(addr));
}
__device__ __forceinline__ void ldm_x4_t(uint32_t* r, uint32_t addr) {
    asm volatile("ldmatrix.sync.aligned.m8n8.x4.trans.shared.b16 {%0,%1,%2,%3}, [%4];"
        : "=r"(r[0]), "=r"(r[1]), "=r"(r[2]), "=r"(r[3]) : "r"(addr));
}

__device__ __forceinline__ void mma_f16(float* d, const uint32_t* a,
                                        uint32_t b0, uint32_t b1) {
    asm volatile(
        "mma.sync.aligned.m16n8k16.row.col.f32.f16.f16.f32 "
        "{%0,%1,%2,%3}, {%4,%5,%6,%7}, {%8,%9}, {%0,%1,%2,%3};"
        : "+f"(d[0]), "+f"(d[1]), "+f"(d[2]), "+f"(d[3])
        : "r"(a[0]), "r"(a[1]), "r"(a[2]), "r"(a[3]), "r"(b0), "r"(b1));
}

// ---------------------------------------------------------------------------
// fp32 -> fp16 hi+lo split / hi-only convert
// ---------------------------------------------------------------------------
__global__ void split_f16(const float* __restrict__ x,
                          __half* __restrict__ hi,
                          __half* __restrict__ lo, size_t n4)
{
    size_t i = (size_t)blockIdx.x * blockDim.x + threadIdx.x;
    if (i >= n4) return;
    float4 v = ((const float4*)x)[i];
    __half h0 = __float2half_rn(v.x);
    __half h1 = __float2half_rn(v.y);
    __half h2 = __float2half_rn(v.z);
    __half h3 = __float2half_rn(v.w);
    __half2 H0; H0.x = h0; H0.y = h1;
    __half2 H1; H1.x = h2; H1.y = h3;
    ((__half2*)hi)[2*i]   = H0;
    ((__half2*)hi)[2*i+1] = H1;
    __half2 L0, L1;
    L0.x = __float2half_rn(v.x - __half2float(h0));
    L0.y = __float2half_rn(v.y - __half2float(h1));
    L1.x = __float2half_rn(v.z - __half2float(h2));
    L1.y = __float2half_rn(v.w - __half2float(h3));
    ((__half2*)lo)[2*i]   = L0;
    ((__half2*)lo)[2*i+1] = L1;
}

__global__ void cvt_f16(const float* __restrict__ x,
                        __half* __restrict__ hi, size_t n4)
{
    size_t i = (size_t)blockIdx.x * blockDim.x + threadIdx.x;
    if (i >= n4) return;
    float4 v = ((const float4*)x)[i];
    __half2 H0; H0.x = __float2half_rn(v.x); H0.y = __float2half_rn(v.y);
    __half2 H1; H1.x = __float2half_rn(v.z); H1.y = __float2half_rn(v.w);
    ((__half2*)hi)[2*i]   = H0;
    ((__half2*)hi)[2*i+1] = H1;
}

// ---------------------------------------------------------------------------
// fp16 HMMA GEMM:  C = A @ B^T
// Per-CTA runtime precision: blockIdx.y < two_term_bn -> (Ah+Al)·Bh, else Ah·Bh.
// CTA 128x128, 8 warps (4M x 2N), warp tile 32x64, BK=32, 2-stage cp.async.
// Cf != nullptr -> fp32 out; else fp16 hi out (+ lo where gcol < lo_limit).
// ---------------------------------------------------------------------------
#define BM 128
#define BN 128
#define BK 32
#define ROWB 80
#define TILEB (128 * ROWB)        // 10240
#define STAGEB (3 * TILEB)        // 30720 (Ah, Al, Bh)
#define GEMM_SMEM (2 * STAGEB)    // 61440
#define GTHREADS 256

__global__ __launch_bounds__(GTHREADS)
void gemm_hmma(const __half* __restrict__ Ah, const __half* __restrict__ Al,
               const __half* __restrict__ Bh,
               float* __restrict__ Cf,
               __half* __restrict__ Ch, __half* __restrict__ Cl,
               int lo_limit, int two_term_bn, int ldc,
               int M, int N, int K)
{
    extern __shared__ char smem[];
    const uint32_t sbase = smem_u32(smem);
    const int tid  = threadIdx.x;
    const int wid  = tid >> 5;
    const int lane = tid & 31;
    const int wm = wid & 3;
    const int wn = wid >> 2;
    const int m0 = blockIdx.x * BM;
    const int n0 = blockIdx.y * BN;
    const int NCH = K / BK;
    const bool two_term = (int)blockIdx.y < two_term_bn;

    // stage loader: tiles Ah(0), Al(1, only if two_term), Bh(2)
    auto load_stage = [&](int s, int kc) {
        const int k0 = kc * BK;
#pragma unroll
        for (int j = 0; j < 6; j++) {
            int id   = tid + j * GTHREADS;   // 0..1535
            int tile = id >> 9;              // 0=Ah 1=Al 2=Bh
            if (tile == 1 && !two_term) continue;
            int idx  = id & 511;
            int row  = idx >> 2;
            int c16  = idx & 3;
            const __half* sb = (tile == 0) ? Ah : (tile == 1) ? Al : Bh;
            int grow = ((tile < 2) ? m0 : n0) + row;
            const void* src = sb + (size_t)grow * K + k0 + c16 * 8;
            uint32_t dst = sbase + s * STAGEB + tile * TILEB + row * ROWB + c16 * 16;
            CP_ASYNC16(dst, src);
        }
        CP_COMMIT();
    };

    float acc[2][8][4];
#pragma unroll
    for (int mi = 0; mi < 2; mi++)
#pragma unroll
        for (int nj = 0; nj < 8; nj++)
#pragma unroll
            for (int q = 0; q < 4; q++) acc[mi][nj][q] = 0.f;

    load_stage(0, 0);
    if (NCH > 1) load_stage(1, 1);

    const int lr = lane & 15;
    const int lc = (lane >> 4) * 16;
    const uint32_t rowA = (wm * 32 + lr) * ROWB + lc;
    const uint32_t rowB = (wn * 64 + lr) * ROWB + lc;

    for (int c = 0; c < NCH; c++) {
        CP_WAIT(1);
        __syncthreads();

        const uint32_t st  = sbase + (c & 1) * STAGEB;
        const uint32_t sAh = st;
        const uint32_t sAl = st + TILEB;
        const uint32_t sBh = st + 2 * TILEB;

#pragma unroll
        for (int kk = 0; kk < 2; kk++) {
            const uint32_t koff = kk * 32;
            uint32_t ahf[2][4], bhf[4][4];
#pragma unroll
            for (int mi = 0; mi < 2; mi++) {
                uint32_t ra = rowA + mi * 16 * ROWB + koff;
                ldm_x4(ahf[mi], sAh + ra);
            }
#pragma unroll
            for (int nj = 0; nj < 4; nj++) {
                uint32_t rb = rowB + nj * 16 * ROWB + koff;
                ldm_x4(bhf[nj], sBh + rb);
            }
            // term 1: Ah * Bh
#pragma unroll
            for (int mi = 0; mi < 2; mi++)
#pragma unroll
                for (int nj = 0; nj < 4; nj++) {
                    mma_f16(acc[mi][2*nj],   ahf[mi], bhf[nj][0], bhf[nj][2]);
                    mma_f16(acc[mi][2*nj+1], ahf[mi], bhf[nj][1], bhf[nj][3]);
                }
            // term 2: Al * Bh (uniform branch; only for two_term CTAs)
            if (two_term) {
                uint32_t alf[2][4];
#pragma unroll
                for (int mi = 0; mi < 2; mi++) {
                    uint32_t ra = rowA + mi * 16 * ROWB + koff;
                    ldm_x4(alf[mi], sAl + ra);
                }
#pragma unroll
                for (int mi = 0; mi < 2; mi++)
#pragma unroll
                    for (int nj = 0; nj < 4; nj++) {
                        mma_f16(acc[mi][2*nj],   alf[mi], bhf[nj][0], bhf[nj][2]);
                        mma_f16(acc[mi][2*nj+1], alf[mi], bhf[nj][1], bhf[nj][3]);
                    }
            }
        }

        __syncthreads();
        if (c + 2 < NCH) load_stage(c & 1, c + 2);
    }

    const int g  = lane >> 2;
    const int cc = (lane & 3) * 2;
#pragma unroll
    for (int mi = 0; mi < 2; mi++) {
        const int rbase = m0 + wm * 32 + mi * 16;
#pragma unroll
        for (int nj = 0; nj < 8; nj++) {
            const int gcol = n0 + wn * 64 + nj * 8 + cc;
            if (Cf) {
                float2 v0 = make_float2(acc[mi][nj][0], acc[mi][nj][1]);
                float2 v1 = make_float2(acc[mi][nj][2], acc[mi][nj][3]);
                *(float2*)&Cf[(size_t)(rbase + g) * ldc + gcol]     = v0;
                *(float2*)&Cf[(size_t)(rbase + g + 8) * ldc + gcol] = v1;
            } else {
#pragma unroll
                for (int rr = 0; rr < 2; rr++) {
                    float x0 = acc[mi][nj][2*rr], x1 = acc[mi][nj][2*rr+1];
                    __half h0 = __float2half_rn(x0);
                    __half h1 = __float2half_rn(x1);
                    __half2 H; H.x = h0; H.y = h1;
                    size_t row = (size_t)(rbase + g + 8*rr);
                    *(__half2*)&Ch[row * ldc + gcol] = H;
                    if (gcol < lo_limit) {
                        __half2 L;
                        L.x = __float2half_rn(x0 - __half2float(h0));
                        L.y = __float2half_rn(x1 - __half2float(h1));
                        *(__half2*)&Cl[row * lo_limit + gcol] = L;
                    }
                }
            }
        }
    }
}

// ---------------------------------------------------------------------------
// fp16 HMMA flash attention. QK 2-term ((Qh+Ql)·Kh), PV 1-term (Ph·Vh).
// P hi-only smem tile -> 113,664 B smem -> 2 CTAs/SM.
// ---------------------------------------------------------------------------
#define AROW 272
#define ATILE (64 * AROW)              // 17408
#define PROW 144
#define PTILE (64 * PROW)              // 9216
#define KSTAGE (2 * ATILE)             // kh, vh = 34816
#define ATTN_SMEM (2*ATILE + 2*KSTAGE + PTILE)   // 113664

__global__ __launch_bounds__(128, 2)
void attn_hmma(const __half* __restrict__ QKVh,
               const __half* __restrict__ Ql_,
               __half* __restrict__ Oh)
{
    extern __shared__ char smem[];
    const uint32_t sb = smem_u32(smem);
    const int tid = threadIdx.x, wid = tid >> 5, lane = tid & 31;
    const int qt = blockIdx.x, h = blockIdx.y, b = blockIdx.z;
    const int q0 = qt * 64;
    const int lr = lane & 15, lc = (lane >> 4) * 16;
    const int g = lane >> 2, t = lane & 3;

    const uint32_t QH_ = sb, QL_ = sb + ATILE;
    const uint32_t KST = sb + 2 * ATILE;
    const uint32_t PH_ = sb + 2 * ATILE + 2 * KSTAGE;

#pragma unroll
    for (int j = 0; j < 8; j++) {
        int id = tid + j * 128;
        int row = id >> 4, c16 = id & 15;
        size_t ghoff = (size_t)(b * SEQ + q0 + row) * QKV_N + h * HDIM + c16 * 8;
        size_t gloff = (size_t)(b * SEQ + q0 + row) * HID   + h * HDIM + c16 * 8;
        CP_ASYNC16(QH_ + row * AROW + c16 * 16, QKVh + ghoff);
        CP_ASYNC16(QL_ + row * AROW + c16 * 16, Ql_  + gloff);
    }
    CP_COMMIT();

    auto load_kv = [&](int s, int kt) {
        const uint32_t base = KST + s * KSTAGE;
        const int k0 = kt * 64;
#pragma unroll
        for (int j = 0; j < 8; j++) {
            int id = tid + j * 128;
            int row = id >> 4, c16 = id & 15;
            size_t grow = (size_t)(b * SEQ + k0 + row) * QKV_N;
            size_t koff = grow + HID     + h * HDIM + c16 * 8;
            size_t voff = grow + 2 * HID + h * HDIM + c16 * 8;
            uint32_t d = row * AROW + c16 * 16;
            CP_ASYNC16(base + d,         QKVh + koff);
            CP_ASYNC16(base + ATILE + d, QKVh + voff);
        }
        CP_COMMIT();
    };

    load_kv(0, 0);

    const float LOG2E = 1.4426950408889634f;
    const float sscale = 0.08838834764831845f * LOG2E;
    const float slope = (h < 32) ? exp2f(-0.25f * (float)(h + 1))
                                 : exp2f(-0.125f * (float)(2 * (h - 32) + 1));
    const float slope2 = slope * LOG2E;

    const int row0 = q0 + wid * 16 + g;
    const int row1 = row0 + 8;

    float m0v = -1e30f, m1v = -1e30f, l0 = 0.f, l1 = 0.f;
    float o[16][4];
#pragma unroll
    for (int i = 0; i < 16; i++)
#pragma unroll
        for (int q = 0; q < 4; q++) o[i][q] = 0.f;

    for (int kt = 0; kt <= qt; kt++) {
        const bool more = (kt + 1 <= qt);
        if (more) load_kv((kt + 1) & 1, kt + 1);
        if (more) { CP_WAIT(1); } else { CP_WAIT(0); }
        __syncthreads();

        const uint32_t KB  = KST + (kt & 1) * KSTAGE;
        const uint32_t KHB = KB;
        const uint32_t VHB = KB + ATILE;

        float sacc[8][4];
#pragma unroll
        for (int nj = 0; nj < 8; nj++)
#pragma unroll
            for (int q = 0; q < 4; q++) sacc[nj][q] = 0.f;

#pragma unroll
        for (int dd = 0; dd < 8; dd++) {
            const uint32_t ra = (wid * 16 + lr) * AROW + dd * 32 + lc;
            uint32_t qhf[4], qlf[4];
            ldm_x4(qhf, QH_ + ra);
            ldm_x4(qlf, QL_ + ra);
            uint32_t khf[4][4];
#pragma unroll
            for (int v = 0; v < 4; v++) {
                const uint32_t rb = (v * 16 + lr) * AROW + dd * 32 + lc;
                ldm_x4(khf[v], KHB + rb);
            }
#pragma unroll
            for (int v = 0; v < 4; v++) {
                mma_f16(sacc[2*v],   qhf, khf[v][0], khf[v][2]);
                mma_f16(sacc[2*v+1], qhf, khf[v][1], khf[v][3]);
            }
#pragma unroll
            for (int v = 0; v < 4; v++) {
                mma_f16(sacc[2*v],   qlf, khf[v][0], khf[v][2]);
                mma_f16(sacc[2*v+1], qlf, khf[v][1], khf[v][3]);
            }
        }

        const int k0 = kt * 64;
        const bool diag = (kt == qt);
        float rmax0 = -1e30f, rmax1 = -1e30f;
#pragma unroll
        for (int nj = 0; nj < 8; nj++) {
#pragma unroll
            for (int e = 0; e < 2; e++) {
                const int col = k0 + nj * 8 + 2 * t + e;
                float v0 = sacc[nj][e]     * sscale + slope2 * (float)col;
                float v1 = sacc[nj][2 + e] * sscale + slope2 * (float)col;
                if (diag) {
                    if (col > row0) v0 = -1e30f;
                    if (col > row1) v1 = -1e30f;
                }
                sacc[nj][e] = v0; sacc[nj][2 + e] = v1;
                rmax0 = fmaxf(rmax0, v0); rmax1 = fmaxf(rmax1, v1);
            }
        }
        rmax0 = fmaxf(rmax0, __shfl_xor_sync(0xffffffffu, rmax0, 1));
        rmax0 = fmaxf(rmax0, __shfl_xor_sync(0xffffffffu, rmax0, 2));
        rmax1 = fmaxf(rmax1, __shfl_xor_sync(0xffffffffu, rmax1, 1));
        rmax1 = fmaxf(rmax1, __shfl_xor_sync(0xffffffffu, rmax1, 2));

        const float mn0 = fmaxf(m0v, rmax0), mn1 = fmaxf(m1v, rmax1);
        const float al0 = exp2f(m0v - mn0),  al1 = exp2f(m1v - mn1);
        m0v = mn0; m1v = mn1;

        float ps0 = 0.f, ps1 = 0.f;
#pragma unroll
        for (int nj = 0; nj < 8; nj++) {
#pragma unroll
            for (int e = 0; e < 2; e++) {
                float p0 = exp2f(sacc[nj][e]     - mn0);
                float p1 = exp2f(sacc[nj][2 + e] - mn1);
                sacc[nj][e] = p0; sacc[nj][2 + e] = p1;
                ps0 += p0; ps1 += p1;
            }
        }
        ps0 += __shfl_xor_sync(0xffffffffu, ps0, 1);
        ps0 += __shfl_xor_sync(0xffffffffu, ps0, 2);
        ps1 += __shfl_xor_sync(0xffffffffu, ps1, 1);
        ps1 += __shfl_xor_sync(0xffffffffu, ps1, 2);
        l0 = l0 * al0 + ps0;
        l1 = l1 * al1 + ps1;

#pragma unroll
        for (int i = 0; i < 16; i++) {
            o[i][0] *= al0; o[i][1] *= al0;
            o[i][2] *= al1; o[i][3] *= al1;
        }

        // write P (hi only) to smem
#pragma unroll
        for (int nj = 0; nj < 8; nj++) {
#pragma unroll
            for (int rr = 0; rr < 2; rr++) {
                float x0 = sacc[nj][2*rr], x1 = sacc[nj][2*rr + 1];
                __half2 H; H.x = __float2half_rn(x0); H.y = __float2half_rn(x1);
                uint32_t off = (wid * 16 + g + 8 * rr) * PROW + (nj * 8 + 2 * t) * 2;
                *(__half2*)(smem + (PH_ - sb) + off) = H;
            }
        }
        __syncwarp();

        // O += Ph * Vh (1-term)
#pragma unroll
        for (int ks = 0; ks < 4; ks++) {
            const uint32_t pa = (wid * 16 + lr) * PROW + ks * 32 + lc;
            uint32_t phf[4];
            ldm_x4(phf, PH_ + pa);
#pragma unroll
            for (int nn = 0; nn < 8; nn++) {
                const uint32_t va = (ks * 16 + lr) * AROW + nn * 32 + lc;
                uint32_t vhf[4];
                ldm_x4_t(vhf, VHB + va);
                mma_f16(o[2*nn],   phf, vhf[0], vhf[1]);
                mma_f16(o[2*nn+1], phf, vhf[2], vhf[3]);
            }
        }
        __syncthreads();
    }

    // epilogue: normalize, hi-only fp16 output (GEMM2 consumes 1-term)
    const float inv0 = 1.0f / l0, inv1 = 1.0f / l1;
#pragma unroll
    for (int i = 0; i < 16; i++) {
        const int col = h * HDIM + i * 8 + 2 * t;
#pragma unroll
        for (int rr = 0; rr < 2; rr++) {
            const float inv = rr ? inv1 : inv0;
            const int row = rr ? row1 : row0;
            float x0 = o[i][2*rr] * inv, x1 = o[i][2*rr + 1] * inv;
            __half2 H; H.x = __float2half_rn(x0); H.y = __float2half_rn(x1);
            *(__half2*)&Oh[(size_t)(b * SEQ + row) * HID + col] = H;
        }
    }
}

// ---------------------------------------------------------------------------
// Launch
// ---------------------------------------------------------------------------
extern "C" void kernel_launch(void* const* d_in, const int* in_sizes, int n_in,
                              void* d_out, int out_size)
{
    const float* hidden = (const float*)d_in[0];
    const float* W_pack = (const float*)d_in[1];
    const float* W_o    = (const float*)d_in[2];
    float* out = (float*)d_out;

    __half *qkvh, *qkvl, *hh, *hl, *ah, *wph, *woh;
    cudaGetSymbolAddress((void**)&qkvh, g_qkvh);
    cudaGetSymbolAddress((void**)&qkvl, g_qkvl);
    cudaGetSymbolAddress((void**)&hh,  g_hh);
    cudaGetSymbolAddress((void**)&hl,  g_hl);
    cudaGetSymbolAddress((void**)&ah,  g_ah);
    cudaGetSymbolAddress((void**)&wph, g_wph);
    cudaGetSymbolAddress((void**)&woh, g_woh);

    cudaFuncSetAttribute(gemm_hmma,
                         cudaFuncAttributeMaxDynamicSharedMemorySize, GEMM_SMEM);
    cudaFuncSetAttribute(attn_hmma,
                         cudaFuncAttributeMaxDynamicSharedMemorySize, ATTN_SMEM);

    {
        size_t n4;
        n4 = (size_t)QKV_N * HID / 4;
        cvt_f16<<<(unsigned)((n4 + 255) / 256), 256>>>(W_pack, wph, n4);
        n4 = (size_t)HID * HID / 4;
        cvt_f16<<<(unsigned)((n4 + 255) / 256), 256>>>(W_o, woh, n4);
        n4 = (size_t)MROWS * HID / 4;
        split_f16<<<(unsigned)((n4 + 255) / 256), 256>>>(hidden, hh, hl, n4);
    }

    // GEMM1 (fused): qkv = hidden @ W_pack^T.
    // Q columns (blockIdx.y < 40): 2-term, hi+lo out. K/V columns: 1-term, hi out.
    gemm_hmma<<<dim3(MROWS/BM, QKV_N/BN), GTHREADS, GEMM_SMEM>>>(
        hh, hl, wph, nullptr, qkvh, qkvl,
        /*lo_limit=*/HID, /*two_term_bn=*/HID/BN, /*ldc=*/QKV_N,
        MROWS, QKV_N, HID);

    // Attention (QK 2-term, PV 1-term, computed ALiBi); hi-only output
    attn_hmma<<<dim3(SEQ/64, NHEAD, BATCH), 128, ATTN_SMEM>>>(qkvh, qkvl, ah);

    // GEMM2: out = attn @ W_o^T, 1-term, fp32 out
    gemm_hmma<<<dim3(MROWS/BM, HID/BN), GTHREADS, GEMM_SMEM>>>(
        ah, nullptr, woh, out, nullptr, nullptr,
        /*lo_limit=*/0, /*two_term_bn=*/0, /*ldc=*/HID,
        MROWS, HID, HID);
}

// round 15
// speedup vs baseline: 1.7016x; 1.2015x over previous
#include <cuda_runtime.h>
#include <cuda_fp16.h>
#include <math.h>
#include <stdint.h>

// Problem constants
#define BATCH 2
#define SEQ   1024
#define HID   5120
#define NHEAD 40
#define HDIM  128
#define QKV_N (3*HID)          // 15360
#define MROWS (BATCH*SEQ)      // 2048

// ---------------------------------------------------------------------------
// Scratch (fp16)
// ---------------------------------------------------------------------------
__device__ __half g_qkvh[(size_t)MROWS * QKV_N];
__device__ __half g_qkvl[(size_t)MROWS * HID];     // lo only needed for Q region
__device__ __half g_hh[(size_t)MROWS * HID];
__device__ __half g_ah[(size_t)MROWS * HID];
__device__ __half g_wph[(size_t)QKV_N * HID];
__device__ __half g_woh[(size_t)HID * HID];

// ---------------------------------------------------------------------------
// PTX helpers (compute_103-safe)
// ---------------------------------------------------------------------------
__device__ __forceinline__ uint32_t smem_u32(const void* p) {
    uint32_t a;
    asm("{ .reg .u64 t; cvta.to.shared.u64 t, %1; cvt.u32.u64 %0, t; }"
        : "=r"(a) : "l"(p));
    return a;
}

#define CP_ASYNC16(dst, src) \
    asm volatile("cp.async.cg.shared.global [%0], [%1], 16;" \
        :: "r"(dst), "l"(src))
#define CP_COMMIT() asm volatile("cp.async.commit_group;" ::: "memory")
#define CP_WAIT(n)  asm volatile("cp.async.wait_group %0;" :: "n"(n) : "memory")

__device__ __forceinline__ void ldm_x4(uint32_t* r, uint32_t addr) {
    asm volatile("ldmatrix.sync.aligned.m8n8.x4.shared.b16 {%0,%1,%2,%3}, [%4];"
        : "=r"(r[0]), "=r"(r[1]), "=r"(r[2]), "=r"(r[3]) : "r"(addr));
}
__device__ __forceinline__ void ldm_x4_t(uint32_t* r, uint32_t addr) {
    asm volatile("ldmatrix.sync.aligned.m8n8.x4.trans.shared.b16 {%0,%1,%2,%3}, [%4];"
        : "=r"(r[0]), "=r"(r[1]), "=r"(r[2]), "=r"(r[3]) : "r"(addr));
}

__device__ __forceinline__ void mma_f16(float* d, const uint32_t* a,
                                        uint32_t b0, uint32_t b1) {
    asm volatile(
        "mma.sync.aligned.m16n8k16.row.col.f32.f16.f16.f32 "
        "{%0,%1,%2,%3}, {%4,%5,%6,%7}, {%8,%9}, {%0,%1,%2,%3};"
        : "+f"(d[0]), "+f"(d[1]), "+f"(d[2]), "+f"(d[3])
        : "r"(a[0]), "r"(a[1]), "r"(a[2]), "r"(a[3]), "r"(b0), "r"(b1));
}

// ---------------------------------------------------------------------------
// fp32 -> fp16 convert
// ---------------------------------------------------------------------------
__global__ void cvt_f16(const float* __restrict__ x,
                        __half* __restrict__ hi, size_t n4)
{
    size_t i = (size_t)blockIdx.x * blockDim.x + threadIdx.x;
    if (i >= n4) return;
    float4 v = ((const float4*)x)[i];
    __half2 H0; H0.x = __float2half_rn(v.x); H0.y = __float2half_rn(v.y);
    __half2 H1; H1.x = __float2half_rn(v.z); H1.y = __float2half_rn(v.w);
    ((__half2*)hi)[2*i]   = H0;
    ((__half2*)hi)[2*i+1] = H1;
}

// ---------------------------------------------------------------------------
// fp16 1-term HMMA GEMM:  C = Ah @ Bh^T
// CTA 128x128, 8 warps (4M x 2N), warp tile 32x64, BK=32, 2-stage cp.async.
// Cf != nullptr -> fp32 out; else fp16 hi out (+ lo where gcol < lo_limit).
// ---------------------------------------------------------------------------
#define BM 128
#define BN 128
#define BK 32
#define ROWB 80
#define TILEB (128 * ROWB)        // 10240
#define STAGEB (2 * TILEB)        // 20480 (Ah, Bh)
#define GEMM_SMEM (2 * STAGEB)    // 40960
#define GTHREADS 256

__global__ __launch_bounds__(GTHREADS)
void gemm_hmma(const __half* __restrict__ Ah,
               const __half* __restrict__ Bh,
               float* __restrict__ Cf,
               __half* __restrict__ Ch, __half* __restrict__ Cl,
               int lo_limit, int ldc,
               int M, int N, int K)
{
    extern __shared__ char smem[];
    const uint32_t sbase = smem_u32(smem);
    const int tid  = threadIdx.x;
    const int wid  = tid >> 5;
    const int lane = tid & 31;
    const int wm = wid & 3;
    const int wn = wid >> 2;
    const int m0 = blockIdx.x * BM;
    const int n0 = blockIdx.y * BN;
    const int NCH = K / BK;

    // stage loader: 1024 16B chunks, 4 per thread (Ah, Bh)
    auto load_stage = [&](int s, int kc) {
        const int k0 = kc * BK;
#pragma unroll
        for (int j = 0; j < 4; j++) {
            int id   = tid + j * GTHREADS;   // 0..1023
            int tile = id >> 9;              // 0=Ah 1=Bh
            int idx  = id & 511;
            int row  = idx >> 2;
            int c16  = idx & 3;
            const __half* sb = tile ? Bh : Ah;
            int grow = (tile ? n0 : m0) + row;
            const void* src = sb + (size_t)grow * K + k0 + c16 * 8;
            uint32_t dst = sbase + s * STAGEB + tile * TILEB + row * ROWB + c16 * 16;
            CP_ASYNC16(dst, src);
        }
        CP_COMMIT();
    };

    float acc[2][8][4];
#pragma unroll
    for (int mi = 0; mi < 2; mi++)
#pragma unroll
        for (int nj = 0; nj < 8; nj++)
#pragma unroll
            for (int q = 0; q < 4; q++) acc[mi][nj][q] = 0.f;

    load_stage(0, 0);
    if (NCH > 1) load_stage(1, 1);

    const int lr = lane & 15;
    const int lc = (lane >> 4) * 16;
    const uint32_t rowA = (wm * 32 + lr) * ROWB + lc;
    const uint32_t rowB = (wn * 64 + lr) * ROWB + lc;

    for (int c = 0; c < NCH; c++) {
        CP_WAIT(1);
        __syncthreads();

        const uint32_t st  = sbase + (c & 1) * STAGEB;
        const uint32_t sAh = st;
        const uint32_t sBh = st + TILEB;

#pragma unroll
        for (int kk = 0; kk < 2; kk++) {
            const uint32_t koff = kk * 32;
            uint32_t ahf[2][4], bhf[4][4];
#pragma unroll
            for (int mi = 0; mi < 2; mi++) {
                uint32_t ra = rowA + mi * 16 * ROWB + koff;
                ldm_x4(ahf[mi], sAh + ra);
            }
#pragma unroll
            for (int nj = 0; nj < 4; nj++) {
                uint32_t rb = rowB + nj * 16 * ROWB + koff;
                ldm_x4(bhf[nj], sBh + rb);
            }
#pragma unroll
            for (int mi = 0; mi < 2; mi++)
#pragma unroll
                for (int nj = 0; nj < 4; nj++) {
                    mma_f16(acc[mi][2*nj],   ahf[mi], bhf[nj][0], bhf[nj][2]);
                    mma_f16(acc[mi][2*nj+1], ahf[mi], bhf[nj][1], bhf[nj][3]);
                }
        }

        __syncthreads();
        if (c + 2 < NCH) load_stage(c & 1, c + 2);
    }

    const int g  = lane >> 2;
    const int cc = (lane & 3) * 2;
#pragma unroll
    for (int mi = 0; mi < 2; mi++) {
        const int rbase = m0 + wm * 32 + mi * 16;
#pragma unroll
        for (int nj = 0; nj < 8; nj++) {
            const int gcol = n0 + wn * 64 + nj * 8 + cc;
            if (Cf) {
                float2 v0 = make_float2(acc[mi][nj][0], acc[mi][nj][1]);
                float2 v1 = make_float2(acc[mi][nj][2], acc[mi][nj][3]);
                *(float2*)&Cf[(size_t)(rbase + g) * ldc + gcol]     = v0;
                *(float2*)&Cf[(size_t)(rbase + g + 8) * ldc + gcol] = v1;
            } else {
#pragma unroll
                for (int rr = 0; rr < 2; rr++) {
                    float x0 = acc[mi][nj][2*rr], x1 = acc[mi][nj][2*rr+1];
                    __half h0 = __float2half_rn(x0);
                    __half h1 = __float2half_rn(x1);
                    __half2 H; H.x = h0; H.y = h1;
                    size_t row = (size_t)(rbase + g + 8*rr);
                    *(__half2*)&Ch[row * ldc + gcol] = H;
                    if (gcol < lo_limit) {
                        __half2 L;
                        L.x = __float2half_rn(x0 - __half2float(h0));
                        L.y = __float2half_rn(x1 - __half2float(h1));
                        *(__half2*)&Cl[row * lo_limit + gcol] = L;
                    }
                }
            }
        }
    }
}

// ---------------------------------------------------------------------------
// fp16 HMMA flash attention. QK 2-term ((Qh+Ql)·Kh), PV 1-term (Ph·Vh).
// 113,664 B smem -> 2 CTAs/SM.
// ---------------------------------------------------------------------------
#define AROW 272
#define ATILE (64 * AROW)              // 17408
#define PROW 144
#define PTILE (64 * PROW)              // 9216
#define KSTAGE (2 * ATILE)             // kh, vh = 34816
#define ATTN_SMEM (2*ATILE + 2*KSTAGE + PTILE)   // 113664

__global__ __launch_bounds__(128, 2)
void attn_hmma(const __half* __restrict__ QKVh,
               const __half* __restrict__ Ql_,
               __half* __restrict__ Oh)
{
    extern __shared__ char smem[];
    const uint32_t sb = smem_u32(smem);
    const int tid = threadIdx.x, wid = tid >> 5, lane = tid & 31;
    const int qt = blockIdx.x, h = blockIdx.y, b = blockIdx.z;
    const int q0 = qt * 64;
    const int lr = lane & 15, lc = (lane >> 4) * 16;
    const int g = lane >> 2, t = lane & 3;

    const uint32_t QH_ = sb, QL_ = sb + ATILE;
    const uint32_t KST = sb + 2 * ATILE;
    const uint32_t PH_ = sb + 2 * ATILE + 2 * KSTAGE;

#pragma unroll
    for (int j = 0; j < 8; j++) {
        int id = tid + j * 128;
        int row = id >> 4, c16 = id & 15;
        size_t ghoff = (size_t)(b * SEQ + q0 + row) * QKV_N + h * HDIM + c16 * 8;
        size_t gloff = (size_t)(b * SEQ + q0 + row) * HID   + h * HDIM + c16 * 8;
        CP_ASYNC16(QH_ + row * AROW + c16 * 16, QKVh + ghoff);
        CP_ASYNC16(QL_ + row * AROW + c16 * 16, Ql_  + gloff);
    }
    CP_COMMIT();

    auto load_kv = [&](int s, int kt) {
        const uint32_t base = KST + s * KSTAGE;
        const int k0 = kt * 64;
#pragma unroll
        for (int j = 0; j < 8; j++) {
            int id = tid + j * 128;
            int row = id >> 4, c16 = id & 15;
            size_t grow = (size_t)(b * SEQ + k0 + row) * QKV_N;
            size_t koff = grow + HID     + h * HDIM + c16 * 8;
            size_t voff = grow + 2 * HID + h * HDIM + c16 * 8;
            uint32_t d = row * AROW + c16 * 16;
            CP_ASYNC16(base + d,         QKVh + koff);
            CP_ASYNC16(base + ATILE + d, QKVh + voff);
        }
        CP_COMMIT();
    };

    load_kv(0, 0);

    const float LOG2E = 1.4426950408889634f;
    const float sscale = 0.08838834764831845f * LOG2E;
    const float slope = (h < 32) ? exp2f(-0.25f * (float)(h + 1))
                                 : exp2f(-0.125f * (float)(2 * (h - 32) + 1));
    const float slope2 = slope * LOG2E;

    const int row0 = q0 + wid * 16 + g;
    const int row1 = row0 + 8;

    float m0v = -1e30f, m1v = -1e30f, l0 = 0.f, l1 = 0.f;
    float o[16][4];
#pragma unroll
    for (int i = 0; i < 16; i++)
#pragma unroll
        for (int q = 0; q < 4; q++) o[i][q] = 0.f;

    for (int kt = 0; kt <= qt; kt++) {
        const bool more = (kt + 1 <= qt);
        if (more) load_kv((kt + 1) & 1, kt + 1);
        if (more) { CP_WAIT(1); } else { CP_WAIT(0); }
        __syncthreads();

        const uint32_t KB  = KST + (kt & 1) * KSTAGE;
        const uint32_t KHB = KB;
        const uint32_t VHB = KB + ATILE;

        float sacc[8][4];
#pragma unroll
        for (int nj = 0; nj < 8; nj++)
#pragma unroll
            for (int q = 0; q < 4; q++) sacc[nj][q] = 0.f;

#pragma unroll
        for (int dd = 0; dd < 8; dd++) {
            const uint32_t ra = (wid * 16 + lr) * AROW + dd * 32 + lc;
            uint32_t qhf[4], qlf[4];
            ldm_x4(qhf, QH_ + ra);
            ldm_x4(qlf, QL_ + ra);
            uint32_t khf[4][4];
#pragma unroll
            for (int v = 0; v < 4; v++) {
                const uint32_t rb = (v * 16 + lr) * AROW + dd * 32 + lc;
                ldm_x4(khf[v], KHB + rb);
            }
#pragma unroll
            for (int v = 0; v < 4; v++) {
                mma_f16(sacc[2*v],   qhf, khf[v][0], khf[v][2]);
                mma_f16(sacc[2*v+1], qhf, khf[v][1], khf[v][3]);
            }
#pragma unroll
            for (int v = 0; v < 4; v++) {
                mma_f16(sacc[2*v],   qlf, khf[v][0], khf[v][2]);
                mma_f16(sacc[2*v+1], qlf, khf[v][1], khf[v][3]);
            }
        }

        const int k0 = kt * 64;
        const bool diag = (kt == qt);
        float rmax0 = -1e30f, rmax1 = -1e30f;
#pragma unroll
        for (int nj = 0; nj < 8; nj++) {
#pragma unroll
            for (int e = 0; e < 2; e++) {
                const int col = k0 + nj * 8 + 2 * t + e;
                float v0 = sacc[nj][e]     * sscale + slope2 * (float)col;
                float v1 = sacc[nj][2 + e] * sscale + slope2 * (float)col;
                if (diag) {
                    if (col > row0) v0 = -1e30f;
                    if (col > row1) v1 = -1e30f;
                }
                sacc[nj][e] = v0; sacc[nj][2 + e] = v1;
                rmax0 = fmaxf(rmax0, v0); rmax1 = fmaxf(rmax1, v1);
            }
        }
        rmax0 = fmaxf(rmax0, __shfl_xor_sync(0xffffffffu, rmax0, 1));
        rmax0 = fmaxf(rmax0, __shfl_xor_sync(0xffffffffu, rmax0, 2));
        rmax1 = fmaxf(rmax1, __shfl_xor_sync(0xffffffffu, rmax1, 1));
        rmax1 = fmaxf(rmax1, __shfl_xor_sync(0xffffffffu, rmax1, 2));

        const float mn0 = fmaxf(m0v, rmax0), mn1 = fmaxf(m1v, rmax1);
        const float al0 = exp2f(m0v - mn0),  al1 = exp2f(m1v - mn1);
        m0v = mn0; m1v = mn1;

        float ps0 = 0.f, ps1 = 0.f;
#pragma unroll
        for (int nj = 0; nj < 8; nj++) {
#pragma unroll
            for (int e = 0; e < 2; e++) {
                float p0 = exp2f(sacc[nj][e]     - mn0);
                float p1 = exp2f(sacc[nj][2 + e] - mn1);
                sacc[nj][e] = p0; sacc[nj][2 + e] = p1;
                ps0 += p0; ps1 += p1;
            }
        }
        ps0 += __shfl_xor_sync(0xffffffffu, ps0, 1);
        ps0 += __shfl_xor_sync(0xffffffffu, ps0, 2);
        ps1 += __shfl_xor_sync(0xffffffffu, ps1, 1);
        ps1 += __shfl_xor_sync(0xffffffffu, ps1, 2);
        l0 = l0 * al0 + ps0;
        l1 = l1 * al1 + ps1;

#pragma unroll
        for (int i = 0; i < 16; i++) {
            o[i][0] *= al0; o[i][1] *= al0;
            o[i][2] *= al1; o[i][3] *= al1;
        }

        // write P (hi only) to smem
#pragma unroll
        for (int nj = 0; nj < 8; nj++) {
#pragma unroll
            for (int rr = 0; rr < 2; rr++) {
                float x0 = sacc[nj][2*rr], x1 = sacc[nj][2*rr + 1];
                __half2 H; H.x = __float2half_rn(x0); H.y = __float2half_rn(x1);
                uint32_t off = (wid * 16 + g + 8 * rr) * PROW + (nj * 8 + 2 * t) * 2;
                *(__half2*)(smem + (PH_ - sb) + off) = H;
            }
        }
        __syncwarp();

        // O += Ph * Vh (1-term)
#pragma unroll
        for (int ks = 0; ks < 4; ks++) {
            const uint32_t pa = (wid * 16 + lr) * PROW + ks * 32 + lc;
            uint32_t phf[4];
            ldm_x4(phf, PH_ + pa);
#pragma unroll
            for (int nn = 0; nn < 8; nn++) {
                const uint32_t va = (ks * 16 + lr) * AROW + nn * 32 + lc;
                uint32_t vhf[4];
                ldm_x4_t(vhf, VHB + va);
                mma_f16(o[2*nn],   phf, vhf[0], vhf[1]);
                mma_f16(o[2*nn+1], phf, vhf[2], vhf[3]);
            }
        }
        __syncthreads();
    }

    // epilogue: normalize, hi-only fp16 output (GEMM2 consumes 1-term)
    const float inv0 = 1.0f / l0, inv1 = 1.0f / l1;
#pragma unroll
    for (int i = 0; i < 16; i++) {
        const int col = h * HDIM + i * 8 + 2 * t;
#pragma unroll
        for (int rr = 0; rr < 2; rr++) {
            const float inv = rr ? inv1 : inv0;
            const int row = rr ? row1 : row0;
            float x0 = o[i][2*rr] * inv, x1 = o[i][2*rr + 1] * inv;
            __half2 H; H.x = __float2half_rn(x0); H.y = __float2half_rn(x1);
            *(__half2*)&Oh[(size_t)(b * SEQ + row) * HID + col] = H;
        }
    }
}

// ---------------------------------------------------------------------------
// Launch
// ---------------------------------------------------------------------------
extern "C" void kernel_launch(void* const* d_in, const int* in_sizes, int n_in,
                              void* d_out, int out_size)
{
    const float* hidden = (const float*)d_in[0];
    const float* W_pack = (const float*)d_in[1];
    const float* W_o    = (const float*)d_in[2];
    float* out = (float*)d_out;

    __half *qkvh, *qkvl, *hh, *ah, *wph, *woh;
    cudaGetSymbolAddress((void**)&qkvh, g_qkvh);
    cudaGetSymbolAddress((void**)&qkvl, g_qkvl);
    cudaGetSymbolAddress((void**)&hh,  g_hh);
    cudaGetSymbolAddress((void**)&ah,  g_ah);
    cudaGetSymbolAddress((void**)&wph, g_wph);
    cudaGetSymbolAddress((void**)&woh, g_woh);

    cudaFuncSetAttribute(gemm_hmma,
                         cudaFuncAttributeMaxDynamicSharedMemorySize, GEMM_SMEM);
    cudaFuncSetAttribute(attn_hmma,
                         cudaFuncAttributeMaxDynamicSharedMemorySize, ATTN_SMEM);

    {
        size_t n4;
        n4 = (size_t)QKV_N * HID / 4;
        cvt_f16<<<(unsigned)((n4 + 255) / 256), 256>>>(W_pack, wph, n4);
        n4 = (size_t)HID * HID / 4;
        cvt_f16<<<(unsigned)((n4 + 255) / 256), 256>>>(W_o, woh, n4);
        n4 = (size_t)MROWS * HID / 4;
        cvt_f16<<<(unsigned)((n4 + 255) / 256), 256>>>(hidden, hh, n4);
    }

    // GEMM1: qkv = hidden @ W_pack^T, 1-term everywhere.
    // Q columns (< HID) also emit the fp16 lo residual for attention's QK.
    gemm_hmma<<<dim3(MROWS/BM, QKV_N/BN), GTHREADS, GEMM_SMEM>>>(
        hh, wph, nullptr, qkvh, qkvl,
        /*lo_limit=*/HID, /*ldc=*/QKV_N,
        MROWS, QKV_N, HID);

    // Attention (QK 2-term, PV 1-term, computed ALiBi); hi-only output
    attn_hmma<<<dim3(SEQ/64, NHEAD, BATCH), 128, ATTN_SMEM>>>(qkvh, qkvl, ah);

    // GEMM2: out = attn @ W_o^T, 1-term, fp32 out
    gemm_hmma<<<dim3(MROWS/BM, HID/BN), GTHREADS, GEMM_SMEM>>>(
        ah, woh, out, nullptr, nullptr,
        /*lo_limit=*/0, /*ldc=*/HID,
        MROWS, HID, HID);
}

// round 16
// speedup vs baseline: 1.9316x; 1.1352x over previous
#include <cuda_runtime.h>
#include <cuda_fp16.h>
#include <math.h>
#include <stdint.h>

// Problem constants
#define BATCH 2
#define SEQ   1024
#define HID   5120
#define NHEAD 40
#define HDIM  128
#define QKV_N (3*HID)          // 15360
#define MROWS (BATCH*SEQ)      // 2048

// ---------------------------------------------------------------------------
// Scratch (fp16)
// ---------------------------------------------------------------------------
__device__ __half g_qkvh[(size_t)MROWS * QKV_N];
__device__ __half g_qkvl[(size_t)MROWS * HID];     // lo only needed for Q region
__device__ __half g_hh[(size_t)MROWS * HID];
__device__ __half g_ah[(size_t)MROWS * HID];
__device__ __half g_wph[(size_t)QKV_N * HID];
__device__ __half g_woh[(size_t)HID * HID];

// ---------------------------------------------------------------------------
// PTX helpers (compute_103-safe)
// ---------------------------------------------------------------------------
__device__ __forceinline__ uint32_t smem_u32(const void* p) {
    uint32_t a;
    asm("{ .reg .u64 t; cvta.to.shared.u64 t, %1; cvt.u32.u64 %0, t; }"
        : "=r"(a) : "l"(p));
    return a;
}

#define CP_ASYNC16(dst, src) \
    asm volatile("cp.async.cg.shared.global [%0], [%1], 16;" \
        :: "r"(dst), "l"(src))
#define CP_COMMIT() asm volatile("cp.async.commit_group;" ::: "memory")
#define CP_WAIT(n)  asm volatile("cp.async.wait_group %0;" :: "n"(n) : "memory")

__device__ __forceinline__ void ldm_x4(uint32_t* r, uint32_t addr) {
    asm volatile("ldmatrix.sync.aligned.m8n8.x4.shared.b16 {%0,%1,%2,%3}, [%4];"
        : "=r"(r[0]), "=r"(r[1]), "=r"(r[2]), "=r"(r[3]) : "r"(addr));
}
__device__ __forceinline__ void ldm_x4_t(uint32_t* r, uint32_t addr) {
    asm volatile("ldmatrix.sync.aligned.m8n8.x4.trans.shared.b16 {%0,%1,%2,%3}, [%4];"
        : "=r"(r[0]), "=r"(r[1]), "=r"(r[2]), "=r"(r[3]) : "r"(addr));
}

__device__ __forceinline__ void mma_f16(float* d, const uint32_t* a,
                                        uint32_t b0, uint32_t b1) {
    asm volatile(
        "mma.sync.aligned.m16n8k16.row.col.f32.f16.f16.f32 "
        "{%0,%1,%2,%3}, {%4,%5,%6,%7}, {%8,%9}, {%0,%1,%2,%3};"
        : "+f"(d[0]), "+f"(d[1]), "+f"(d[2]), "+f"(d[3])
        : "r"(a[0]), "r"(a[1]), "r"(a[2]), "r"(a[3]), "r"(b0), "r"(b1));
}

// ---------------------------------------------------------------------------
// fp32 -> fp16 convert
// ---------------------------------------------------------------------------
__global__ void cvt_f16(const float* __restrict__ x,
                        __half* __restrict__ hi, size_t n4)
{
    size_t i = (size_t)blockIdx.x * blockDim.x + threadIdx.x;
    if (i >= n4) return;
    float4 v = ((const float4*)x)[i];
    __half2 H0; H0.x = __float2half_rn(v.x); H0.y = __float2half_rn(v.y);
    __half2 H1; H1.x = __float2half_rn(v.z); H1.y = __float2half_rn(v.w);
    ((__half2*)hi)[2*i]   = H0;
    ((__half2*)hi)[2*i+1] = H1;
}

// ---------------------------------------------------------------------------
// fp16 1-term HMMA GEMM:  C = Ah @ Bh^T
// CTA 128x128, 8 warps (4M x 2N), warp tile 32x64, BK=64, 2-stage cp.async.
// 73.7KB smem -> 2 CTAs/SM; half the barrier events of BK=32.
// Cf != nullptr -> fp32 out; else fp16 hi out (+ lo where gcol < lo_limit).
// ---------------------------------------------------------------------------
#define BM 128
#define BN 128
#define BK 64
#define ROWB 144                  // 64 fp16 = 128B + 16B pad
#define TILEB (128 * ROWB)        // 18432
#define STAGEB (2 * TILEB)        // 36864 (Ah, Bh)
#define GEMM_SMEM (2 * STAGEB)    // 73728
#define GTHREADS 256

__global__ __launch_bounds__(GTHREADS)
void gemm_hmma(const __half* __restrict__ Ah,
               const __half* __restrict__ Bh,
               float* __restrict__ Cf,
               __half* __restrict__ Ch, __half* __restrict__ Cl,
               int lo_limit, int ldc,
               int M, int N, int K)
{
    extern __shared__ char smem[];
    const uint32_t sbase = smem_u32(smem);
    const int tid  = threadIdx.x;
    const int wid  = tid >> 5;
    const int lane = tid & 31;
    const int wm = wid & 3;
    const int wn = wid >> 2;
    const int m0 = blockIdx.x * BM;
    const int n0 = blockIdx.y * BN;
    const int NCH = K / BK;

    // stage loader: 2048 16B chunks, 8 per thread (Ah, Bh; 8 x 16B per row)
    auto load_stage = [&](int s, int kc) {
        const int k0 = kc * BK;
#pragma unroll
        for (int j = 0; j < 8; j++) {
            int id   = tid + j * GTHREADS;   // 0..2047
            int tile = id >> 10;             // 0=Ah 1=Bh
            int idx  = id & 1023;
            int row  = idx >> 3;             // 0..127
            int c16  = idx & 7;              // 0..7
            const __half* sb = tile ? Bh : Ah;
            int grow = (tile ? n0 : m0) + row;
            const void* src = sb + (size_t)grow * K + k0 + c16 * 8;
            uint32_t dst = sbase + s * STAGEB + tile * TILEB + row * ROWB + c16 * 16;
            CP_ASYNC16(dst, src);
        }
        CP_COMMIT();
    };

    float acc[2][8][4];
#pragma unroll
    for (int mi = 0; mi < 2; mi++)
#pragma unroll
        for (int nj = 0; nj < 8; nj++)
#pragma unroll
            for (int q = 0; q < 4; q++) acc[mi][nj][q] = 0.f;

    load_stage(0, 0);
    if (NCH > 1) load_stage(1, 1);

    const int lr = lane & 15;
    const int lc = (lane >> 4) * 16;
    const uint32_t rowA = (wm * 32 + lr) * ROWB + lc;
    const uint32_t rowB = (wn * 64 + lr) * ROWB + lc;

    for (int c = 0; c < NCH; c++) {
        CP_WAIT(1);
        __syncthreads();

        const uint32_t st  = sbase + (c & 1) * STAGEB;
        const uint32_t sAh = st;
        const uint32_t sBh = st + TILEB;

#pragma unroll
        for (int kk = 0; kk < 4; kk++) {          // 4 k16 blocks (BK=64)
            const uint32_t koff = kk * 32;
            uint32_t ahf[2][4], bhf[4][4];
#pragma unroll
            for (int mi = 0; mi < 2; mi++) {
                uint32_t ra = rowA + mi * 16 * ROWB + koff;
                ldm_x4(ahf[mi], sAh + ra);
            }
#pragma unroll
            for (int nj = 0; nj < 4; nj++) {
                uint32_t rb = rowB + nj * 16 * ROWB + koff;
                ldm_x4(bhf[nj], sBh + rb);
            }
#pragma unroll
            for (int mi = 0; mi < 2; mi++)
#pragma unroll
                for (int nj = 0; nj < 4; nj++) {
                    mma_f16(acc[mi][2*nj],   ahf[mi], bhf[nj][0], bhf[nj][2]);
                    mma_f16(acc[mi][2*nj+1], ahf[mi], bhf[nj][1], bhf[nj][3]);
                }
        }

        __syncthreads();
        if (c + 2 < NCH) load_stage(c & 1, c + 2);
    }

    const int g  = lane >> 2;
    const int cc = (lane & 3) * 2;
#pragma unroll
    for (int mi = 0; mi < 2; mi++) {
        const int rbase = m0 + wm * 32 + mi * 16;
#pragma unroll
        for (int nj = 0; nj < 8; nj++) {
            const int gcol = n0 + wn * 64 + nj * 8 + cc;
            if (Cf) {
                float2 v0 = make_float2(acc[mi][nj][0], acc[mi][nj][1]);
                float2 v1 = make_float2(acc[mi][nj][2], acc[mi][nj][3]);
                *(float2*)&Cf[(size_t)(rbase + g) * ldc + gcol]     = v0;
                *(float2*)&Cf[(size_t)(rbase + g + 8) * ldc + gcol] = v1;
            } else {
#pragma unroll
                for (int rr = 0; rr < 2; rr++) {
                    float x0 = acc[mi][nj][2*rr], x1 = acc[mi][nj][2*rr+1];
                    __half h0 = __float2half_rn(x0);
                    __half h1 = __float2half_rn(x1);
                    __half2 H; H.x = h0; H.y = h1;
                    size_t row = (size_t)(rbase + g + 8*rr);
                    *(__half2*)&Ch[row * ldc + gcol] = H;
                    if (gcol < lo_limit) {
                        __half2 L;
                        L.x = __float2half_rn(x0 - __half2float(h0));
                        L.y = __float2half_rn(x1 - __half2float(h1));
                        *(__half2*)&Cl[row * lo_limit + gcol] = L;
                    }
                }
            }
        }
    }
}

// ---------------------------------------------------------------------------
// fp16 HMMA flash attention. QK 2-term ((Qh+Ql)·Kh), PV 1-term (Ph·Vh).
// 113,664 B smem -> 2 CTAs/SM.
// ---------------------------------------------------------------------------
#define AROW 272
#define ATILE (64 * AROW)              // 17408
#define PROW 144
#define PTILE (64 * PROW)              // 9216
#define KSTAGE (2 * ATILE)             // kh, vh = 34816
#define ATTN_SMEM (2*ATILE + 2*KSTAGE + PTILE)   // 113664

__global__ __launch_bounds__(128, 2)
void attn_hmma(const __half* __restrict__ QKVh,
               const __half* __restrict__ Ql_,
               __half* __restrict__ Oh)
{
    extern __shared__ char smem[];
    const uint32_t sb = smem_u32(smem);
    const int tid = threadIdx.x, wid = tid >> 5, lane = tid & 31;
    const int qt = blockIdx.x, h = blockIdx.y, b = blockIdx.z;
    const int q0 = qt * 64;
    const int lr = lane & 15, lc = (lane >> 4) * 16;
    const int g = lane >> 2, t = lane & 3;

    const uint32_t QH_ = sb, QL_ = sb + ATILE;
    const uint32_t KST = sb + 2 * ATILE;
    const uint32_t PH_ = sb + 2 * ATILE + 2 * KSTAGE;

#pragma unroll
    for (int j = 0; j < 8; j++) {
        int id = tid + j * 128;
        int row = id >> 4, c16 = id & 15;
        size_t ghoff = (size_t)(b * SEQ + q0 + row) * QKV_N + h * HDIM + c16 * 8;
        size_t gloff = (size_t)(b * SEQ + q0 + row) * HID   + h * HDIM + c16 * 8;
        CP_ASYNC16(QH_ + row * AROW + c16 * 16, QKVh + ghoff);
        CP_ASYNC16(QL_ + row * AROW + c16 * 16, Ql_  + gloff);
    }
    CP_COMMIT();

    auto load_kv = [&](int s, int kt) {
        const uint32_t base = KST + s * KSTAGE;
        const int k0 = kt * 64;
#pragma unroll
        for (int j = 0; j < 8; j++) {
            int id = tid + j * 128;
            int row = id >> 4, c16 = id & 15;
            size_t grow = (size_t)(b * SEQ + k0 + row) * QKV_N;
            size_t koff = grow + HID     + h * HDIM + c16 * 8;
            size_t voff = grow + 2 * HID + h * HDIM + c16 * 8;
            uint32_t d = row * AROW + c16 * 16;
            CP_ASYNC16(base + d,         QKVh + koff);
            CP_ASYNC16(base + ATILE + d, QKVh + voff);
        }
        CP_COMMIT();
    };

    load_kv(0, 0);

    const float LOG2E = 1.4426950408889634f;
    const float sscale = 0.08838834764831845f * LOG2E;
    const float slope = (h < 32) ? exp2f(-0.25f * (float)(h + 1))
                                 : exp2f(-0.125f * (float)(2 * (h - 32) + 1));
    const float slope2 = slope * LOG2E;

    const int row0 = q0 + wid * 16 + g;
    const int row1 = row0 + 8;

    float m0v = -1e30f, m1v = -1e30f, l0 = 0.f, l1 = 0.f;
    float o[16][4];
#pragma unroll
    for (int i = 0; i < 16; i++)
#pragma unroll
        for (int q = 0; q < 4; q++) o[i][q] = 0.f;

    for (int kt = 0; kt <= qt; kt++) {
        const bool more = (kt + 1 <= qt);
        if (more) load_kv((kt + 1) & 1, kt + 1);
        if (more) { CP_WAIT(1); } else { CP_WAIT(0); }
        __syncthreads();

        const uint32_t KB  = KST + (kt & 1) * KSTAGE;
        const uint32_t KHB = KB;
        const uint32_t VHB = KB + ATILE;

        float sacc[8][4];
#pragma unroll
        for (int nj = 0; nj < 8; nj++)
#pragma unroll
            for (int q = 0; q < 4; q++) sacc[nj][q] = 0.f;

#pragma unroll
        for (int dd = 0; dd < 8; dd++) {
            const uint32_t ra = (wid * 16 + lr) * AROW + dd * 32 + lc;
            uint32_t qhf[4], qlf[4];
            ldm_x4(qhf, QH_ + ra);
            ldm_x4(qlf, QL_ + ra);
            uint32_t khf[4][4];
#pragma unroll
            for (int v = 0; v < 4; v++) {
                const uint32_t rb = (v * 16 + lr) * AROW + dd * 32 + lc;
                ldm_x4(khf[v], KHB + rb);
            }
#pragma unroll
            for (int v = 0; v < 4; v++) {
                mma_f16(sacc[2*v],   qhf, khf[v][0], khf[v][2]);
                mma_f16(sacc[2*v+1], qhf, khf[v][1], khf[v][3]);
            }
#pragma unroll
            for (int v = 0; v < 4; v++) {
                mma_f16(sacc[2*v],   qlf, khf[v][0], khf[v][2]);
                mma_f16(sacc[2*v+1], qlf, khf[v][1], khf[v][3]);
            }
        }

        const int k0 = kt * 64;
        const bool diag = (kt == qt);
        float rmax0 = -1e30f, rmax1 = -1e30f;
#pragma unroll
        for (int nj = 0; nj < 8; nj++) {
#pragma unroll
            for (int e = 0; e < 2; e++) {
                const int col = k0 + nj * 8 + 2 * t + e;
                float v0 = sacc[nj][e]     * sscale + slope2 * (float)col;
                float v1 = sacc[nj][2 + e] * sscale + slope2 * (float)col;
                if (diag) {
                    if (col > row0) v0 = -1e30f;
                    if (col > row1) v1 = -1e30f;
                }
                sacc[nj][e] = v0; sacc[nj][2 + e] = v1;
                rmax0 = fmaxf(rmax0, v0); rmax1 = fmaxf(rmax1, v1);
            }
        }
        rmax0 = fmaxf(rmax0, __shfl_xor_sync(0xffffffffu, rmax0, 1));
        rmax0 = fmaxf(rmax0, __shfl_xor_sync(0xffffffffu, rmax0, 2));
        rmax1 = fmaxf(rmax1, __shfl_xor_sync(0xffffffffu, rmax1, 1));
        rmax1 = fmaxf(rmax1, __shfl_xor_sync(0xffffffffu, rmax1, 2));

        const float mn0 = fmaxf(m0v, rmax0), mn1 = fmaxf(m1v, rmax1);
        const float al0 = exp2f(m0v - mn0),  al1 = exp2f(m1v - mn1);
        m0v = mn0; m1v = mn1;

        float ps0 = 0.f, ps1 = 0.f;
#pragma unroll
        for (int nj = 0; nj < 8; nj++) {
#pragma unroll
            for (int e = 0; e < 2; e++) {
                float p0 = exp2f(sacc[nj][e]     - mn0);
                float p1 = exp2f(sacc[nj][2 + e] - mn1);
                sacc[nj][e] = p0; sacc[nj][2 + e] = p1;
                ps0 += p0; ps1 += p1;
            }
        }
        ps0 += __shfl_xor_sync(0xffffffffu, ps0, 1);
        ps0 += __shfl_xor_sync(0xffffffffu, ps0, 2);
        ps1 += __shfl_xor_sync(0xffffffffu, ps1, 1);
        ps1 += __shfl_xor_sync(0xffffffffu, ps1, 2);
        l0 = l0 * al0 + ps0;
        l1 = l1 * al1 + ps1;

#pragma unroll
        for (int i = 0; i < 16; i++) {
            o[i][0] *= al0; o[i][1] *= al0;
            o[i][2] *= al1; o[i][3] *= al1;
        }

        // write P (hi only) to smem
#pragma unroll
        for (int nj = 0; nj < 8; nj++) {
#pragma unroll
            for (int rr = 0; rr < 2; rr++) {
                float x0 = sacc[nj][2*rr], x1 = sacc[nj][2*rr + 1];
                __half2 H; H.x = __float2half_rn(x0); H.y = __float2half_rn(x1);
                uint32_t off = (wid * 16 + g + 8 * rr) * PROW + (nj * 8 + 2 * t) * 2;
                *(__half2*)(smem + (PH_ - sb) + off) = H;
            }
        }
        __syncwarp();

        // O += Ph * Vh (1-term)
#pragma unroll
        for (int ks = 0; ks < 4; ks++) {
            const uint32_t pa = (wid * 16 + lr) * PROW + ks * 32 + lc;
            uint32_t phf[4];
            ldm_x4(phf, PH_ + pa);
#pragma unroll
            for (int nn = 0; nn < 8; nn++) {
                const uint32_t va = (ks * 16 + lr) * AROW + nn * 32 + lc;
                uint32_t vhf[4];
                ldm_x4_t(vhf, VHB + va);
                mma_f16(o[2*nn],   phf, vhf[0], vhf[1]);
                mma_f16(o[2*nn+1], phf, vhf[2], vhf[3]);
            }
        }
        __syncthreads();
    }

    // epilogue: normalize, hi-only fp16 output (GEMM2 consumes 1-term)
    const float inv0 = 1.0f / l0, inv1 = 1.0f / l1;
#pragma unroll
    for (int i = 0; i < 16; i++) {
        const int col = h * HDIM + i * 8 + 2 * t;
#pragma unroll
        for (int rr = 0; rr < 2; rr++) {
            const float inv = rr ? inv1 : inv0;
            const int row = rr ? row1 : row0;
            float x0 = o[i][2*rr] * inv, x1 = o[i][2*rr + 1] * inv;
            __half2 H; H.x = __float2half_rn(x0); H.y = __float2half_rn(x1);
            *(__half2*)&Oh[(size_t)(b * SEQ + row) * HID + col] = H;
        }
    }
}

// ---------------------------------------------------------------------------
// Launch
// ---------------------------------------------------------------------------
extern "C" void kernel_launch(void* const* d_in, const int* in_sizes, int n_in,
                              void* d_out, int out_size)
{
    const float* hidden = (const float*)d_in[0];
    const float* W_pack = (const float*)d_in[1];
    const float* W_o    = (const float*)d_in[2];
    float* out = (float*)d_out;

    __half *qkvh, *qkvl, *hh, *ah, *wph, *woh;
    cudaGetSymbolAddress((void**)&qkvh, g_qkvh);
    cudaGetSymbolAddress((void**)&qkvl, g_qkvl);
    cudaGetSymbolAddress((void**)&hh,  g_hh);
    cudaGetSymbolAddress((void**)&ah,  g_ah);
    cudaGetSymbolAddress((void**)&wph, g_wph);
    cudaGetSymbolAddress((void**)&woh, g_woh);

    cudaFuncSetAttribute(gemm_hmma,
                         cudaFuncAttributeMaxDynamicSharedMemorySize, GEMM_SMEM);
    cudaFuncSetAttribute(attn_hmma,
                         cudaFuncAttributeMaxDynamicSharedMemorySize, ATTN_SMEM);

    {
        size_t n4;
        n4 = (size_t)QKV_N * HID / 4;
        cvt_f16<<<(unsigned)((n4 + 255) / 256), 256>>>(W_pack, wph, n4);
        n4 = (size_t)HID * HID / 4;
        cvt_f16<<<(unsigned)((n4 + 255) / 256), 256>>>(W_o, woh, n4);
        n4 = (size_t)MROWS * HID / 4;
        cvt_f16<<<(unsigned)((n4 + 255) / 256), 256>>>(hidden, hh, n4);
    }

    // GEMM1: qkv = hidden @ W_pack^T, 1-term everywhere.
    // Q columns (< HID) also emit the fp16 lo residual for attention's QK.
    gemm_hmma<<<dim3(MROWS/BM, QKV_N/BN), GTHREADS, GEMM_SMEM>>>(
        hh, wph, nullptr, qkvh, qkvl,
        /*lo_limit=*/HID, /*ldc=*/QKV_N,
        MROWS, QKV_N, HID);

    // Attention (QK 2-term, PV 1-term, computed ALiBi); hi-only output
    attn_hmma<<<dim3(SEQ/64, NHEAD, BATCH), 128, ATTN_SMEM>>>(qkvh, qkvl, ah);

    // GEMM2: out = attn @ W_o^T, 1-term, fp32 out
    gemm_hmma<<<dim3(MROWS/BM, HID/BN), GTHREADS, GEMM_SMEM>>>(
        ah, woh, out, nullptr, nullptr,
        /*lo_limit=*/0, /*ldc=*/HID,
        MROWS, HID, HID);
}

// round 17
// speedup vs baseline: 1.9656x; 1.0176x over previous
#include <cuda_runtime.h>
#include <cuda_fp16.h>
#include <math.h>
#include <stdint.h>

// Problem constants
#define BATCH 2
#define SEQ   1024
#define HID   5120
#define NHEAD 40
#define HDIM  128
#define QKV_N (3*HID)          // 15360
#define MROWS (BATCH*SEQ)      // 2048

// ---------------------------------------------------------------------------
// Scratch (fp16)
// ---------------------------------------------------------------------------
__device__ __half g_qkvh[(size_t)MROWS * QKV_N];
__device__ __half g_qkvl[(size_t)MROWS * HID];     // lo only needed for Q region
__device__ __half g_hh[(size_t)MROWS * HID];
__device__ __half g_ah[(size_t)MROWS * HID];
__device__ __half g_wph[(size_t)QKV_N * HID];
__device__ __half g_woh[(size_t)HID * HID];

// ---------------------------------------------------------------------------
// PTX helpers (compute_103-safe)
// ---------------------------------------------------------------------------
__device__ __forceinline__ uint32_t smem_u32(const void* p) {
    uint32_t a;
    asm("{ .reg .u64 t; cvta.to.shared.u64 t, %1; cvt.u32.u64 %0, t; }"
        : "=r"(a) : "l"(p));
    return a;
}

#define CP_ASYNC16(dst, src) \
    asm volatile("cp.async.cg.shared.global [%0], [%1], 16;" \
        :: "r"(dst), "l"(src))
#define CP_COMMIT() asm volatile("cp.async.commit_group;" ::: "memory")
#define CP_WAIT(n)  asm volatile("cp.async.wait_group %0;" :: "n"(n) : "memory")

__device__ __forceinline__ void ldm_x4(uint32_t* r, uint32_t addr) {
    asm volatile("ldmatrix.sync.aligned.m8n8.x4.shared.b16 {%0,%1,%2,%3}, [%4];"
        : "=r"(r[0]), "=r"(r[1]), "=r"(r[2]), "=r"(r[3]) : "r"(addr));
}
__device__ __forceinline__ void ldm_x4_t(uint32_t* r, uint32_t addr) {
    asm volatile("ldmatrix.sync.aligned.m8n8.x4.trans.shared.b16 {%0,%1,%2,%3}, [%4];"
        : "=r"(r[0]), "=r"(r[1]), "=r"(r[2]), "=r"(r[3]) : "r"(addr));
}

__device__ __forceinline__ void mma_f16(float* d, const uint32_t* a,
                                        uint32_t b0, uint32_t b1) {
    asm volatile(
        "mma.sync.aligned.m16n8k16.row.col.f32.f16.f16.f32 "
        "{%0,%1,%2,%3}, {%4,%5,%6,%7}, {%8,%9}, {%0,%1,%2,%3};"
        : "+f"(d[0]), "+f"(d[1]), "+f"(d[2]), "+f"(d[3])
        : "r"(a[0]), "r"(a[1]), "r"(a[2]), "r"(a[3]), "r"(b0), "r"(b1));
}

// ---------------------------------------------------------------------------
// fused fp32 -> fp16 convert over three segments (W_pack, W_o, hidden)
// ---------------------------------------------------------------------------
__global__ void cvt_f16_all(const float* __restrict__ x0, __half* __restrict__ y0, size_t n0,
                            const float* __restrict__ x1, __half* __restrict__ y1, size_t n1,
                            const float* __restrict__ x2, __half* __restrict__ y2, size_t n2)
{
    size_t i = (size_t)blockIdx.x * blockDim.x + threadIdx.x;
    const float* x; __half* y; size_t k;
    if (i < n0)               { x = x0; y = y0; k = i; }
    else if (i < n0 + n1)     { x = x1; y = y1; k = i - n0; }
    else if (i < n0 + n1 + n2){ x = x2; y = y2; k = i - n0 - n1; }
    else return;
    float4 v = ((const float4*)x)[k];
    __half2 H0; H0.x = __float2half_rn(v.x); H0.y = __float2half_rn(v.y);
    __half2 H1; H1.x = __float2half_rn(v.z); H1.y = __float2half_rn(v.w);
    ((__half2*)y)[2*k]   = H0;
    ((__half2*)y)[2*k+1] = H1;
}

// ---------------------------------------------------------------------------
// fp16 1-term HMMA GEMM:  C = Ah @ Bh^T
// CTA 128x128, 8 warps (4M x 2N), warp tile 32x64, BK=64.
// 3-stage cp.async pipeline, ONE barrier per chunk (loads for c+2 reuse the
// buffer vacated by c-1, guaranteed free by the top-of-loop barrier).
// 110.6KB smem -> 2 CTAs/SM.
// Cf != nullptr -> fp32 out; else fp16 hi out (+ lo where gcol < lo_limit).
// ---------------------------------------------------------------------------
#define BM 128
#define BN 128
#define BK 64
#define ROWB 144                  // 64 fp16 = 128B + 16B pad
#define TILEB (128 * ROWB)        // 18432
#define STAGEB (2 * TILEB)        // 36864 (Ah, Bh)
#define NSTAGE 3
#define GEMM_SMEM (NSTAGE * STAGEB)  // 110592
#define GTHREADS 256

__global__ __launch_bounds__(GTHREADS)
void gemm_hmma(const __half* __restrict__ Ah,
               const __half* __restrict__ Bh,
               float* __restrict__ Cf,
               __half* __restrict__ Ch, __half* __restrict__ Cl,
               int lo_limit, int ldc,
               int M, int N, int K)
{
    extern __shared__ char smem[];
    const uint32_t sbase = smem_u32(smem);
    const int tid  = threadIdx.x;
    const int wid  = tid >> 5;
    const int lane = tid & 31;
    const int wm = wid & 3;
    const int wn = wid >> 2;
    const int m0 = blockIdx.x * BM;
    const int n0 = blockIdx.y * BN;
    const int NCH = K / BK;

    // stage loader: 2048 16B chunks, 8 per thread (Ah, Bh; 8 x 16B per row)
    auto load_stage = [&](int s, int kc) {
        const int k0 = kc * BK;
#pragma unroll
        for (int j = 0; j < 8; j++) {
            int id   = tid + j * GTHREADS;   // 0..2047
            int tile = id >> 10;             // 0=Ah 1=Bh
            int idx  = id & 1023;
            int row  = idx >> 3;             // 0..127
            int c16  = idx & 7;              // 0..7
            const __half* sb = tile ? Bh : Ah;
            int grow = (tile ? n0 : m0) + row;
            const void* src = sb + (size_t)grow * K + k0 + c16 * 8;
            uint32_t dst = sbase + s * STAGEB + tile * TILEB + row * ROWB + c16 * 16;
            CP_ASYNC16(dst, src);
        }
        CP_COMMIT();
    };

    float acc[2][8][4];
#pragma unroll
    for (int mi = 0; mi < 2; mi++)
#pragma unroll
        for (int nj = 0; nj < 8; nj++)
#pragma unroll
            for (int q = 0; q < 4; q++) acc[mi][nj][q] = 0.f;

    load_stage(0, 0);
    if (NCH > 1) load_stage(1, 1);

    const int lr = lane & 15;
    const int lc = (lane >> 4) * 16;
    const uint32_t rowA = (wm * 32 + lr) * ROWB + lc;
    const uint32_t rowB = (wn * 64 + lr) * ROWB + lc;

    int sidx = 0;
    for (int c = 0; c < NCH; c++) {
        CP_WAIT(1);
        __syncthreads();   // stage sidx ready; buffer (sidx+2)%3 free (compute c-1 done)

        if (c + 2 < NCH) {
            int s2 = sidx + 2; if (s2 >= NSTAGE) s2 -= NSTAGE;
            load_stage(s2, c + 2);
        }

        const uint32_t st  = sbase + sidx * STAGEB;
        const uint32_t sAh = st;
        const uint32_t sBh = st + TILEB;

#pragma unroll
        for (int kk = 0; kk < 4; kk++) {          // 4 k16 blocks (BK=64)
            const uint32_t koff = kk * 32;
            uint32_t ahf[2][4], bhf[4][4];
#pragma unroll
            for (int mi = 0; mi < 2; mi++) {
                uint32_t ra = rowA + mi * 16 * ROWB + koff;
                ldm_x4(ahf[mi], sAh + ra);
            }
#pragma unroll
            for (int nj = 0; nj < 4; nj++) {
                uint32_t rb = rowB + nj * 16 * ROWB + koff;
                ldm_x4(bhf[nj], sBh + rb);
            }
#pragma unroll
            for (int mi = 0; mi < 2; mi++)
#pragma unroll
                for (int nj = 0; nj < 4; nj++) {
                    mma_f16(acc[mi][2*nj],   ahf[mi], bhf[nj][0], bhf[nj][2]);
                    mma_f16(acc[mi][2*nj+1], ahf[mi], bhf[nj][1], bhf[nj][3]);
                }
        }

        if (++sidx >= NSTAGE) sidx -= NSTAGE;
    }

    const int g  = lane >> 2;
    const int cc = (lane & 3) * 2;
#pragma unroll
    for (int mi = 0; mi < 2; mi++) {
        const int rbase = m0 + wm * 32 + mi * 16;
#pragma unroll
        for (int nj = 0; nj < 8; nj++) {
            const int gcol = n0 + wn * 64 + nj * 8 + cc;
            if (Cf) {
                float2 v0 = make_float2(acc[mi][nj][0], acc[mi][nj][1]);
                float2 v1 = make_float2(acc[mi][nj][2], acc[mi][nj][3]);
                *(float2*)&Cf[(size_t)(rbase + g) * ldc + gcol]     = v0;
                *(float2*)&Cf[(size_t)(rbase + g + 8) * ldc + gcol] = v1;
            } else {
#pragma unroll
                for (int rr = 0; rr < 2; rr++) {
                    float x0 = acc[mi][nj][2*rr], x1 = acc[mi][nj][2*rr+1];
                    __half h0 = __float2half_rn(x0);
                    __half h1 = __float2half_rn(x1);
                    __half2 H; H.x = h0; H.y = h1;
                    size_t row = (size_t)(rbase + g + 8*rr);
                    *(__half2*)&Ch[row * ldc + gcol] = H;
                    if (gcol < lo_limit) {
                        __half2 L;
                        L.x = __float2half_rn(x0 - __half2float(h0));
                        L.y = __float2half_rn(x1 - __half2float(h1));
                        *(__half2*)&Cl[row * lo_limit + gcol] = L;
                    }
                }
            }
        }
    }
}

// ---------------------------------------------------------------------------
// fp16 HMMA flash attention. QK 2-term ((Qh+Ql)·Kh), PV 1-term (Ph·Vh).
// 113,664 B smem -> 2 CTAs/SM. Heavy q-tiles launch first (qt reversed).
// ---------------------------------------------------------------------------
#define AROW 272
#define ATILE (64 * AROW)              // 17408
#define PROW 144
#define PTILE (64 * PROW)              // 9216
#define KSTAGE (2 * ATILE)             // kh, vh = 34816
#define ATTN_SMEM (2*ATILE + 2*KSTAGE + PTILE)   // 113664

__global__ __launch_bounds__(128, 2)
void attn_hmma(const __half* __restrict__ QKVh,
               const __half* __restrict__ Ql_,
               __half* __restrict__ Oh)
{
    extern __shared__ char smem[];
    const uint32_t sb = smem_u32(smem);
    const int tid = threadIdx.x, wid = tid >> 5, lane = tid & 31;
    const int qt = gridDim.x - 1 - blockIdx.x;   // heavy tiles first
    const int h = blockIdx.y, b = blockIdx.z;
    const int q0 = qt * 64;
    const int lr = lane & 15, lc = (lane >> 4) * 16;
    const int g = lane >> 2, t = lane & 3;

    const uint32_t QH_ = sb, QL_ = sb + ATILE;
    const uint32_t KST = sb + 2 * ATILE;
    const uint32_t PH_ = sb + 2 * ATILE + 2 * KSTAGE;

#pragma unroll
    for (int j = 0; j < 8; j++) {
        int id = tid + j * 128;
        int row = id >> 4, c16 = id & 15;
        size_t ghoff = (size_t)(b * SEQ + q0 + row) * QKV_N + h * HDIM + c16 * 8;
        size_t gloff = (size_t)(b * SEQ + q0 + row) * HID   + h * HDIM + c16 * 8;
        CP_ASYNC16(QH_ + row * AROW + c16 * 16, QKVh + ghoff);
        CP_ASYNC16(QL_ + row * AROW + c16 * 16, Ql_  + gloff);
    }
    CP_COMMIT();

    auto load_kv = [&](int s, int kt) {
        const uint32_t base = KST + s * KSTAGE;
        const int k0 = kt * 64;
#pragma unroll
        for (int j = 0; j < 8; j++) {
            int id = tid + j * 128;
            int row = id >> 4, c16 = id & 15;
            size_t grow = (size_t)(b * SEQ + k0 + row) * QKV_N;
            size_t koff = grow + HID     + h * HDIM + c16 * 8;
            size_t voff = grow + 2 * HID + h * HDIM + c16 * 8;
            uint32_t d = row * AROW + c16 * 16;
            CP_ASYNC16(base + d,         QKVh + koff);
            CP_ASYNC16(base + ATILE + d, QKVh + voff);
        }
        CP_COMMIT();
    };

    load_kv(0, 0);

    const float LOG2E = 1.4426950408889634f;
    const float sscale = 0.08838834764831845f * LOG2E;
    const float slope = (h < 32) ? exp2f(-0.25f * (float)(h + 1))
                                 : exp2f(-0.125f * (float)(2 * (h - 32) + 1));
    const float slope2 = slope * LOG2E;

    const int row0 = q0 + wid * 16 + g;
    const int row1 = row0 + 8;

    float m0v = -1e30f, m1v = -1e30f, l0 = 0.f, l1 = 0.f;
    float o[16][4];
#pragma unroll
    for (int i = 0; i < 16; i++)
#pragma unroll
        for (int q = 0; q < 4; q++) o[i][q] = 0.f;

    for (int kt = 0; kt <= qt; kt++) {
        const bool more = (kt + 1 <= qt);
        if (more) load_kv((kt + 1) & 1, kt + 1);
        if (more) { CP_WAIT(1); } else { CP_WAIT(0); }
        __syncthreads();

        const uint32_t KB  = KST + (kt & 1) * KSTAGE;
        const uint32_t KHB = KB;
        const uint32_t VHB = KB + ATILE;

        float sacc[8][4];
#pragma unroll
        for (int nj = 0; nj < 8; nj++)
#pragma unroll
            for (int q = 0; q < 4; q++) sacc[nj][q] = 0.f;

#pragma unroll
        for (int dd = 0; dd < 8; dd++) {
            const uint32_t ra = (wid * 16 + lr) * AROW + dd * 32 + lc;
            uint32_t qhf[4], qlf[4];
            ldm_x4(qhf, QH_ + ra);
            ldm_x4(qlf, QL_ + ra);
            uint32_t khf[4][4];
#pragma unroll
            for (int v = 0; v < 4; v++) {
                const uint32_t rb = (v * 16 + lr) * AROW + dd * 32 + lc;
                ldm_x4(khf[v], KHB + rb);
            }
#pragma unroll
            for (int v = 0; v < 4; v++) {
                mma_f16(sacc[2*v],   qhf, khf[v][0], khf[v][2]);
                mma_f16(sacc[2*v+1], qhf, khf[v][1], khf[v][3]);
            }
#pragma unroll
            for (int v = 0; v < 4; v++) {
                mma_f16(sacc[2*v],   qlf, khf[v][0], khf[v][2]);
                mma_f16(sacc[2*v+1], qlf, khf[v][1], khf[v][3]);
            }
        }

        const int k0 = kt * 64;
        const bool diag = (kt == qt);
        float rmax0 = -1e30f, rmax1 = -1e30f;
#pragma unroll
        for (int nj = 0; nj < 8; nj++) {
#pragma unroll
            for (int e = 0; e < 2; e++) {
                const int col = k0 + nj * 8 + 2 * t + e;
                float v0 = sacc[nj][e]     * sscale + slope2 * (float)col;
                float v1 = sacc[nj][2 + e] * sscale + slope2 * (float)col;
                if (diag) {
                    if (col > row0) v0 = -1e30f;
                    if (col > row1) v1 = -1e30f;
                }
                sacc[nj][e] = v0; sacc[nj][2 + e] = v1;
                rmax0 = fmaxf(rmax0, v0); rmax1 = fmaxf(rmax1, v1);
            }
        }
        rmax0 = fmaxf(rmax0, __shfl_xor_sync(0xffffffffu, rmax0, 1));
        rmax0 = fmaxf(rmax0, __shfl_xor_sync(0xffffffffu, rmax0, 2));
        rmax1 = fmaxf(rmax1, __shfl_xor_sync(0xffffffffu, rmax1, 1));
        rmax1 = fmaxf(rmax1, __shfl_xor_sync(0xffffffffu, rmax1, 2));

        const float mn0 = fmaxf(m0v, rmax0), mn1 = fmaxf(m1v, rmax1);
        const float al0 = exp2f(m0v - mn0),  al1 = exp2f(m1v - mn1);
        m0v = mn0; m1v = mn1;

        float ps0 = 0.f, ps1 = 0.f;
#pragma unroll
        for (int nj = 0; nj < 8; nj++) {
#pragma unroll
            for (int e = 0; e < 2; e++) {
                float p0 = exp2f(sacc[nj][e]     - mn0);
                float p1 = exp2f(sacc[nj][2 + e] - mn1);
                sacc[nj][e] = p0; sacc[nj][2 + e] = p1;
                ps0 += p0; ps1 += p1;
            }
        }
        ps0 += __shfl_xor_sync(0xffffffffu, ps0, 1);
        ps0 += __shfl_xor_sync(0xffffffffu, ps0, 2);
        ps1 += __shfl_xor_sync(0xffffffffu, ps1, 1);
        ps1 += __shfl_xor_sync(0xffffffffu, ps1, 2);
        l0 = l0 * al0 + ps0;
        l1 = l1 * al1 + ps1;

#pragma unroll
        for (int i = 0; i < 16; i++) {
            o[i][0] *= al0; o[i][1] *= al0;
            o[i][2] *= al1; o[i][3] *= al1;
        }

        // write P (hi only) to smem
#pragma unroll
        for (int nj = 0; nj < 8; nj++) {
#pragma unroll
            for (int rr = 0; rr < 2; rr++) {
                float x0 = sacc[nj][2*rr], x1 = sacc[nj][2*rr + 1];
                __half2 H; H.x = __float2half_rn(x0); H.y = __float2half_rn(x1);
                uint32_t off = (wid * 16 + g + 8 * rr) * PROW + (nj * 8 + 2 * t) * 2;
                *(__half2*)(smem + (PH_ - sb) + off) = H;
            }
        }
        __syncwarp();

        // O += Ph * Vh (1-term)
#pragma unroll
        for (int ks = 0; ks < 4; ks++) {
            const uint32_t pa = (wid * 16 + lr) * PROW + ks * 32 + lc;
            uint32_t phf[4];
            ldm_x4(phf, PH_ + pa);
#pragma unroll
            for (int nn = 0; nn < 8; nn++) {
                const uint32_t va = (ks * 16 + lr) * AROW + nn * 32 + lc;
                uint32_t vhf[4];
                ldm_x4_t(vhf, VHB + va);
                mma_f16(o[2*nn],   phf, vhf[0], vhf[1]);
                mma_f16(o[2*nn+1], phf, vhf[2], vhf[3]);
            }
        }
        __syncthreads();
    }

    // epilogue: normalize, hi-only fp16 output (GEMM2 consumes 1-term)
    const float inv0 = 1.0f / l0, inv1 = 1.0f / l1;
#pragma unroll
    for (int i = 0; i < 16; i++) {
        const int col = h * HDIM + i * 8 + 2 * t;
#pragma unroll
        for (int rr = 0; rr < 2; rr++) {
            const float inv = rr ? inv1 : inv0;
            const int row = rr ? row1 : row0;
            float x0 = o[i][2*rr] * inv, x1 = o[i][2*rr + 1] * inv;
            __half2 H; H.x = __float2half_rn(x0); H.y = __float2half_rn(x1);
            *(__half2*)&Oh[(size_t)(b * SEQ + row) * HID + col] = H;
        }
    }
}

// ---------------------------------------------------------------------------
// Launch
// ---------------------------------------------------------------------------
extern "C" void kernel_launch(void* const* d_in, const int* in_sizes, int n_in,
                              void* d_out, int out_size)
{
    const float* hidden = (const float*)d_in[0];
    const float* W_pack = (const float*)d_in[1];
    const float* W_o    = (const float*)d_in[2];
    float* out = (float*)d_out;

    __half *qkvh, *qkvl, *hh, *ah, *wph, *woh;
    cudaGetSymbolAddress((void**)&qkvh, g_qkvh);
    cudaGetSymbolAddress((void**)&qkvl, g_qkvl);
    cudaGetSymbolAddress((void**)&hh,  g_hh);
    cudaGetSymbolAddress((void**)&ah,  g_ah);
    cudaGetSymbolAddress((void**)&wph, g_wph);
    cudaGetSymbolAddress((void**)&woh, g_woh);

    cudaFuncSetAttribute(gemm_hmma,
                         cudaFuncAttributeMaxDynamicSharedMemorySize, GEMM_SMEM);
    cudaFuncSetAttribute(attn_hmma,
                         cudaFuncAttributeMaxDynamicSharedMemorySize, ATTN_SMEM);

    // fused fp32 -> fp16 conversions (one launch)
    {
        size_t n0 = (size_t)QKV_N * HID / 4;   // W_pack
        size_t n1 = (size_t)HID * HID / 4;     // W_o
        size_t n2 = (size_t)MROWS * HID / 4;   // hidden
        size_t tot = n0 + n1 + n2;
        cvt_f16_all<<<(unsigned)((tot + 255) / 256), 256>>>(
            W_pack, wph, n0, W_o, woh, n1, hidden, hh, n2);
    }

    // GEMM1: qkv = hidden @ W_pack^T, 1-term everywhere.
    // Q columns (< HID) also emit the fp16 lo residual for attention's QK.
    gemm_hmma<<<dim3(MROWS/BM, QKV_N/BN), GTHREADS, GEMM_SMEM>>>(
        hh, wph, nullptr, qkvh, qkvl,
        /*lo_limit=*/HID, /*ldc=*/QKV_N,
        MROWS, QKV_N, HID);

    // Attention (QK 2-term, PV 1-term, computed ALiBi); hi-only output
    attn_hmma<<<dim3(SEQ/64, NHEAD, BATCH), 128, ATTN_SMEM>>>(qkvh, qkvl, ah);

    // GEMM2: out = attn @ W_o^T, 1-term, fp32 out
    gemm_hmma<<<dim3(MROWS/BM, HID/BN), GTHREADS, GEMM_SMEM>>>(
        ah, woh, out, nullptr, nullptr,
        /*lo_limit=*/0, /*ldc=*/HID,
        MROWS, HID, HID);
}